// round 2
// baseline (speedup 1.0000x reference)
#include <cuda_runtime.h>
#include <math.h>
#include <float.h>
#include <stdint.h>

#define B_  4
#define L_  1024
#define D_  512
#define H_  8
#define HD_ 64
#define PROJ_ELEMS (2*B_*H_*L_*HD_)   /* 4,194,304 */
#define MASK_ELEMS ((size_t)B_*L_*L_) /* 4,194,304 */

__device__ float g_q[PROJ_ELEMS];
__device__ float g_k[PROJ_ELEMS];
__device__ float g_v[PROJ_ELEMS];
__device__ float g_ctx[PROJ_ELEMS];
__device__ float g_bpp[L_*L_];
__device__ float g_bppT[L_*L_];
__device__ unsigned char g_mue[B_*L_*L_];
__device__ unsigned char g_meu[B_*L_*L_];
__device__ int g_mtype;

// ---------------------------------------------------------------------------
// Mask dtype detection: inspect raw words of ue_mask.
//   int32 bool  -> every 32-bit word in {0,1}
//   float32     -> words in {0, 0x3F800000}
//   bfloat16    -> words in {0, 0x3F800000, 0x00003F80, 0x3F803F80}
//   uint8 bool  -> none of the above (e.g. 0x01010101)
// ---------------------------------------------------------------------------
__global__ void mask_detect_kernel(const unsigned int* __restrict__ m)
{
    __shared__ int viol[3];
    if (threadIdx.x < 3) viol[threadIdx.x] = 0;
    __syncthreads();
    int v0 = 0, v1 = 0, v2 = 0;
    for (int i = threadIdx.x; i < 16384; i += 256) {
        unsigned w = m[i];
        if (w > 1u) v0 = 1;
        if (w != 0u && w != 0x3F800000u) v1 = 1;
        if (w != 0u && w != 0x3F800000u && w != 0x00003F80u && w != 0x3F803F80u) v2 = 1;
    }
    if (v0) atomicOr(&viol[0], 1);
    if (v1) atomicOr(&viol[1], 1);
    if (v2) atomicOr(&viol[2], 1);
    __syncthreads();
    if (threadIdx.x == 0) {
        int t;
        if      (!viol[0]) t = 1;   // int32
        else if (!viol[1]) t = 2;   // float32
        else if (!viol[2]) t = 3;   // bf16
        else               t = 0;   // uint8
        g_mtype = t;
    }
}

// ---------------------------------------------------------------------------
// Expand masks (any encoding) into flat uint8 [B][L][L]
// grid (4096,1,2) x 256
// ---------------------------------------------------------------------------
__global__ __launch_bounds__(256) void mask_expand_kernel(
    const void* __restrict__ ue, const void* __restrict__ eu)
{
    int t = g_mtype;
    const void* src = blockIdx.z ? eu : ue;
    unsigned char* dst = blockIdx.z ? g_meu : g_mue;
    size_t stride = (size_t)gridDim.x * blockDim.x;
    for (size_t i = (size_t)blockIdx.x*blockDim.x + threadIdx.x;
         i < MASK_ELEMS; i += stride) {
        unsigned char v;
        if      (t == 1) v = ((const int*)src)[i] != 0;
        else if (t == 2) v = ((const float*)src)[i] != 0.f;
        else if (t == 3) v = ((const unsigned short*)src)[i] != 0;
        else             v = ((const unsigned char*)src)[i] != 0;
        dst[i] = v;
    }
}

// ---------------------------------------------------------------------------
// bpp prep: g_bpp = bpp_w*logit_bpp + bpp_b ; g_bppT = transpose(g_bpp)
// block (32,8), grid (32,32)
// ---------------------------------------------------------------------------
__global__ __launch_bounds__(256) void bpp_prep_kernel(
    const float* __restrict__ lb,
    const float* __restrict__ wp,
    const float* __restrict__ bp)
{
    __shared__ float t[32][33];
    int tx = threadIdx.x, ty = threadIdx.y;
    float w = wp[0], bb = bp[0];
    int x  = blockIdx.x*32 + tx;
    int y0 = blockIdx.y*32;
    #pragma unroll
    for (int i = ty; i < 32; i += 8) {
        float v = fmaf(w, lb[(size_t)(y0+i)*L_ + x], bb);
        g_bpp[(size_t)(y0+i)*L_ + x] = v;
        t[i][tx] = v;
    }
    __syncthreads();
    int xo = y0 + tx;
    #pragma unroll
    for (int i = ty; i < 32; i += 8) {
        g_bppT[(size_t)(blockIdx.x*32+i)*L_ + xo] = t[tx][i];
    }
}

// ---------------------------------------------------------------------------
// GEMM: [8192 x 512] * [512 x 512] + bias.
//   mode 0/1/2 (qkv): A rows 0..4095 from A0(u_enc), 4096.. from A1(e_enc);
//                     output scattered to g_q/g_k/g_v as [enc][b][h][l][hd];
//                     mode 0 applies scale 1/sqrt(HD)=0.125 after bias.
//   mode 3 (out-proj): A = g_ctx, output to outp row-major [8192 x 512].
// Tile 128(M) x 64(N) x 16(K), 256 threads, 8x4 microtile.
// ---------------------------------------------------------------------------
__global__ __launch_bounds__(256) void gemm_kernel(
    const float* __restrict__ A0, const float* __restrict__ A1,
    const float* __restrict__ Wq, const float* __restrict__ Wk,
    const float* __restrict__ Wv,
    const float* __restrict__ bq, const float* __restrict__ bk,
    const float* __restrict__ bv,
    float* __restrict__ outp, int modebase)
{
    __shared__ float As[128*17];
    __shared__ float Bs[16*68];

    int mode = modebase + blockIdx.z;
    const float* W; const float* bias; float* dst;
    if      (mode == 0) { W = Wq; bias = bq; dst = g_q; }
    else if (mode == 1) { W = Wk; bias = bk; dst = g_k; }
    else if (mode == 2) { W = Wv; bias = bv; dst = g_v; }
    else                { W = Wq; bias = bq; dst = outp; }

    const float* Abase0 = (modebase == 3) ? g_ctx : A0;
    const float* Abase1 = (modebase == 3) ? (g_ctx + (size_t)4096*D_) : A1;

    int tid  = threadIdx.x;
    int tx   = tid & 15, ty = tid >> 4;
    int n0   = blockIdx.x * 64;
    int row0 = blockIdx.y * 128;
    const float* A = (row0 < 4096) ? Abase0 : Abase1;
    int ar0 = (row0 < 4096) ? row0 : row0 - 4096;

    float acc[8][4];
    #pragma unroll
    for (int i = 0; i < 8; i++)
        #pragma unroll
        for (int j = 0; j < 4; j++) acc[i][j] = 0.f;

    for (int kb = 0; kb < 32; kb++) {
        int kbase = kb * 16;
        #pragma unroll
        for (int i = 0; i < 2; i++) {
            int e4 = i*256 + tid;
            int m  = e4 >> 2;
            int k4 = (e4 & 3) * 4;
            float4 v = *(const float4*)&A[(size_t)(ar0+m)*D_ + kbase + k4];
            As[m*17 + k4+0] = v.x; As[m*17 + k4+1] = v.y;
            As[m*17 + k4+2] = v.z; As[m*17 + k4+3] = v.w;
        }
        {
            int kk = tid >> 4, n4 = (tid & 15) * 4;
            float4 v = *(const float4*)&W[(size_t)(kbase+kk)*D_ + n0 + n4];
            *(float4*)&Bs[kk*68 + n4] = v;
        }
        __syncthreads();
        #pragma unroll
        for (int kk = 0; kk < 16; kk++) {
            float a[8];
            #pragma unroll
            for (int i = 0; i < 8; i++) a[i] = As[(ty*8+i)*17 + kk];
            float4 b4 = *(const float4*)&Bs[kk*68 + tx*4];
            #pragma unroll
            for (int i = 0; i < 8; i++) {
                acc[i][0] = fmaf(a[i], b4.x, acc[i][0]);
                acc[i][1] = fmaf(a[i], b4.y, acc[i][1]);
                acc[i][2] = fmaf(a[i], b4.z, acc[i][2]);
                acc[i][3] = fmaf(a[i], b4.w, acc[i][3]);
            }
        }
        __syncthreads();
    }

    float bsv[4];
    #pragma unroll
    for (int j = 0; j < 4; j++) bsv[j] = bias[n0 + tx*4 + j];
    float scale = (mode == 0) ? 0.125f : 1.f;

    #pragma unroll
    for (int i = 0; i < 8; i++) {
        int R = row0 + ty*8 + i;
        float4 o;
        o.x = (acc[i][0] + bsv[0]) * scale;
        o.y = (acc[i][1] + bsv[1]) * scale;
        o.z = (acc[i][2] + bsv[2]) * scale;
        o.w = (acc[i][3] + bsv[3]) * scale;
        if (mode < 3) {
            int enc = R >> 12, b = (R >> 10) & 3, l = R & 1023;
            int h = n0 >> 6;
            size_t idx = ((((size_t)(enc*B_ + b))*H_ + h)*L_ + l)*HD_ + tx*4;
            *(float4*)&dst[idx] = o;
        } else {
            *(float4*)&dst[(size_t)R*D_ + n0 + tx*4] = o;
        }
    }
}

// ---------------------------------------------------------------------------
// Fused flash attention (fp32). grid (16 qtiles, 32 b*h, 2 dirs), 256 thr.
// ---------------------------------------------------------------------------
__global__ __launch_bounds__(256) void attn_kernel()
{
    extern __shared__ float sm[];
    float* q_s = sm;
    float* k_s = sm + 64*65;
    float* v_s = sm + 2*64*65;
    float* p_s = sm + 3*64*65;

    int tid = threadIdx.x, tx = tid & 15, ty = tid >> 4;
    int qt = blockIdx.x, bh = blockIdx.y, dir = blockIdx.z;
    int b = bh >> 3, h = bh & 7;
    int enc_q = dir, enc_kv = 1 - dir;

    const float* Qg = g_q + ((size_t)((enc_q *B_ + b)*H_ + h))*L_*HD_;
    const float* Kg = g_k + ((size_t)((enc_kv*B_ + b)*H_ + h))*L_*HD_;
    const float* Vg = g_v + ((size_t)((enc_kv*B_ + b)*H_ + h))*L_*HD_;
    const unsigned char* Mk = (dir == 0 ? g_mue : g_meu) + (size_t)b*L_*L_;
    const float* Bp = (dir == 0) ? g_bpp : g_bppT;
    int q0 = qt * 64;

    #pragma unroll
    for (int i = 0; i < 16; i++) {
        int e = i*256 + tid;
        int r = e >> 6, hd = e & 63;
        q_s[hd*65 + r] = Qg[(size_t)(q0+r)*64 + hd];
    }

    float o[4][4];
    float mreg[4], lreg[4];
    #pragma unroll
    for (int i = 0; i < 4; i++) {
        mreg[i] = -3.0e38f; lreg[i] = 0.f;
        #pragma unroll
        for (int j = 0; j < 4; j++) o[i][j] = 0.f;
    }

    for (int t = 0; t < 16; t++) {
        int k0 = t * 64;
        __syncthreads();
        #pragma unroll
        for (int i = 0; i < 16; i++) {
            int e = i*256 + tid;
            int r = e >> 6, hd = e & 63;
            k_s[hd*65 + r] = Kg[(size_t)(k0+r)*64 + hd];
            v_s[r*65 + hd] = Vg[(size_t)(k0+r)*64 + hd];
        }
        __syncthreads();

        float s[4][4];
        #pragma unroll
        for (int i = 0; i < 4; i++)
            #pragma unroll
            for (int j = 0; j < 4; j++) s[i][j] = 0.f;

        #pragma unroll 8
        for (int kk = 0; kk < 64; kk++) {
            float qv[4], kv[4];
            #pragma unroll
            for (int i = 0; i < 4; i++) qv[i] = q_s[kk*65 + ty*4 + i];
            #pragma unroll
            for (int j = 0; j < 4; j++) kv[j] = k_s[kk*65 + tx*4 + j];
            #pragma unroll
            for (int i = 0; i < 4; i++)
                #pragma unroll
                for (int j = 0; j < 4; j++)
                    s[i][j] = fmaf(qv[i], kv[j], s[i][j]);
        }

        #pragma unroll
        for (int i = 0; i < 4; i++) {
            int qg = q0 + ty*4 + i;
            const float*         bprow = Bp + (size_t)qg*L_ + k0 + tx*4;
            const unsigned char* mrow  = Mk + (size_t)qg*L_ + k0 + tx*4;
            #pragma unroll
            for (int j = 0; j < 4; j++) {
                float sv = s[i][j] + bprow[j];
                s[i][j] = mrow[j] ? sv : -3.0e38f;
            }
        }

        #pragma unroll
        for (int i = 0; i < 4; i++) {
            float mx = fmaxf(fmaxf(s[i][0], s[i][1]), fmaxf(s[i][2], s[i][3]));
            mx = fmaxf(mx, __shfl_xor_sync(0xffffffffu, mx, 8));
            mx = fmaxf(mx, __shfl_xor_sync(0xffffffffu, mx, 4));
            mx = fmaxf(mx, __shfl_xor_sync(0xffffffffu, mx, 2));
            mx = fmaxf(mx, __shfl_xor_sync(0xffffffffu, mx, 1));
            float mnew = fmaxf(mreg[i], mx);
            float corr = __expf(mreg[i] - mnew);
            float p0 = __expf(s[i][0] - mnew);
            float p1 = __expf(s[i][1] - mnew);
            float p2 = __expf(s[i][2] - mnew);
            float p3 = __expf(s[i][3] - mnew);
            float rs = (p0 + p1) + (p2 + p3);
            rs += __shfl_xor_sync(0xffffffffu, rs, 8);
            rs += __shfl_xor_sync(0xffffffffu, rs, 4);
            rs += __shfl_xor_sync(0xffffffffu, rs, 2);
            rs += __shfl_xor_sync(0xffffffffu, rs, 1);
            lreg[i] = lreg[i]*corr + rs;
            mreg[i] = mnew;
            #pragma unroll
            for (int j = 0; j < 4; j++) o[i][j] *= corr;
            int pr = (ty*4 + i)*65 + tx*4;
            p_s[pr+0] = p0; p_s[pr+1] = p1; p_s[pr+2] = p2; p_s[pr+3] = p3;
        }
        __syncthreads();

        #pragma unroll 8
        for (int kk = 0; kk < 64; kk++) {
            float pv[4], vv[4];
            #pragma unroll
            for (int i = 0; i < 4; i++) pv[i] = p_s[(ty*4+i)*65 + kk];
            #pragma unroll
            for (int j = 0; j < 4; j++) vv[j] = v_s[kk*65 + tx*4 + j];
            #pragma unroll
            for (int i = 0; i < 4; i++)
                #pragma unroll
                for (int j = 0; j < 4; j++)
                    o[i][j] = fmaf(pv[i], vv[j], o[i][j]);
        }
    }

    #pragma unroll
    for (int i = 0; i < 4; i++) {
        float inv = 1.f / lreg[i];
        float4 ov;
        ov.x = o[i][0]*inv; ov.y = o[i][1]*inv;
        ov.z = o[i][2]*inv; ov.w = o[i][3]*inv;
        size_t idx = ((size_t)((enc_q*B_ + b))*L_ + q0 + ty*4 + i)*D_
                     + h*64 + tx*4;
        *(float4*)&g_ctx[idx] = ov;
    }
}

// ---------------------------------------------------------------------------
extern "C" void kernel_launch(void* const* d_in, const int* in_sizes, int n_in,
                              void* d_out, int out_size)
{
    const float* u_enc     = (const float*)d_in[0];
    const float* e_enc     = (const float*)d_in[1];
    const float* logit_bpp = (const float*)d_in[2];
    const void*  ue_mask   = d_in[3];
    const void*  eu_mask   = d_in[4];
    const float* wq_k = (const float*)d_in[5];
    const float* wq_b = (const float*)d_in[6];
    const float* wk_k = (const float*)d_in[7];
    const float* wk_b = (const float*)d_in[8];
    const float* wv_k = (const float*)d_in[9];
    const float* wv_b = (const float*)d_in[10];
    const float* wo_k = (const float*)d_in[11];
    const float* wo_b = (const float*)d_in[12];
    const float* bpp_w = (const float*)d_in[13];
    const float* bpp_b = (const float*)d_in[14];
    float* out = (float*)d_out;

    const int ATTN_SMEM = 4*64*65*sizeof(float);   // 66,560 B
    cudaFuncSetAttribute((const void*)attn_kernel,
                         cudaFuncAttributeMaxDynamicSharedMemorySize, ATTN_SMEM);

    // 0) mask dtype detection + expansion to uint8
    mask_detect_kernel<<<1, 256>>>((const unsigned int*)ue_mask);
    mask_expand_kernel<<<dim3(4096, 1, 2), 256>>>(ue_mask, eu_mask);
    // 1) fused QKV projections (z: 0=q,1=k,2=v)
    gemm_kernel<<<dim3(8, 64, 3), 256>>>(u_enc, e_enc,
                                         wq_k, wk_k, wv_k,
                                         wq_b, wk_b, wv_b,
                                         nullptr, 0);
    // 2) bias prep (bpp and bpp^T with scalars folded)
    bpp_prep_kernel<<<dim3(32, 32), dim3(32, 8)>>>(logit_bpp, bpp_w, bpp_b);
    // 3) fused attention, both directions
    attn_kernel<<<dim3(16, 32, 2), 256, ATTN_SMEM>>>();
    // 4) output projection -> d_out ([u_update ; e_update])
    gemm_kernel<<<dim3(8, 64, 1), 256>>>(nullptr, nullptr,
                                         wo_k, nullptr, nullptr,
                                         wo_b, nullptr, nullptr,
                                         out, 3);
}

// round 4
// speedup vs baseline: 1.1792x; 1.1792x over previous
#include <cuda_runtime.h>
#include <cuda_bf16.h>
#include <math.h>
#include <float.h>
#include <stdint.h>
#include <string.h>

#define B_  4
#define L_  1024
#define D_  512
#define H_  8
#define HD_ 64
#define PROJ_ELEMS (2*B_*H_*L_*HD_)   /* 4,194,304 */
#define MASK_ELEMS ((size_t)B_*L_*L_) /* 4,194,304 */

__device__ float g_q[PROJ_ELEMS];
__device__ float g_k[PROJ_ELEMS];
__device__ float g_v[PROJ_ELEMS];
__device__ float g_ctx[PROJ_ELEMS];
__device__ float g_bpp[L_*L_];
__device__ float g_bppT[L_*L_];
__device__ unsigned char g_mue[B_*L_*L_];
__device__ unsigned char g_meu[B_*L_*L_];
__device__ int g_mtype;

// ===========================================================================
// mma.sync helpers (base PTX — compute_103 virtual arch has no tcgen05)
// ===========================================================================
__device__ __forceinline__ uint32_t smem_u32(const void* p) {
    uint32_t a;
    asm("{ .reg .u64 t; cvta.to.shared.u64 t, %1; cvt.u32.u64 %0, t; }"
        : "=r"(a) : "l"(p));
    return a;
}
__device__ __forceinline__ void ldsm_x4(uint32_t& r0, uint32_t& r1,
                                        uint32_t& r2, uint32_t& r3,
                                        uint32_t addr) {
    asm volatile("ldmatrix.sync.aligned.m8n8.x4.shared.b16 {%0,%1,%2,%3}, [%4];"
                 : "=r"(r0), "=r"(r1), "=r"(r2), "=r"(r3) : "r"(addr));
}
__device__ __forceinline__ void mma_bf16(float* c, const uint32_t* a,
                                         const uint32_t* b) {
    asm volatile("mma.sync.aligned.m16n8k16.row.col.f32.bf16.bf16.f32 "
                 "{%0,%1,%2,%3}, {%4,%5,%6,%7}, {%8,%9}, {%0,%1,%2,%3};"
                 : "+f"(c[0]), "+f"(c[1]), "+f"(c[2]), "+f"(c[3])
                 : "r"(a[0]), "r"(a[1]), "r"(a[2]), "r"(a[3]),
                   "r"(b[0]), "r"(b[1]));
}
__device__ __forceinline__ unsigned short f2bf_bits(float x) {
    __nv_bfloat16 h = __float2bfloat16(x);
    unsigned short u; memcpy(&u, &h, 2); return u;
}
__device__ __forceinline__ float bfbits2f(unsigned short u) {
    __nv_bfloat16 h; memcpy(&h, &u, 2); return __bfloat162float(h);
}
// pack hi pair + lo pair from two floats
__device__ __forceinline__ void split2(float x, float y, uint32_t& hi, uint32_t& lo) {
    unsigned short hx = f2bf_bits(x), hy = f2bf_bits(y);
    unsigned short lx = f2bf_bits(x - bfbits2f(hx));
    unsigned short ly = f2bf_bits(y - bfbits2f(hy));
    hi = (uint32_t)hx | ((uint32_t)hy << 16);
    lo = (uint32_t)lx | ((uint32_t)ly << 16);
}

// ===========================================================================
// Mask dtype detect + expand (unchanged)
// ===========================================================================
__global__ void mask_detect_kernel(const unsigned int* __restrict__ m)
{
    __shared__ int viol[3];
    if (threadIdx.x < 3) viol[threadIdx.x] = 0;
    __syncthreads();
    int v0 = 0, v1 = 0, v2 = 0;
    for (int i = threadIdx.x; i < 16384; i += 256) {
        unsigned w = m[i];
        if (w > 1u) v0 = 1;
        if (w != 0u && w != 0x3F800000u) v1 = 1;
        if (w != 0u && w != 0x3F800000u && w != 0x00003F80u && w != 0x3F803F80u) v2 = 1;
    }
    if (v0) atomicOr(&viol[0], 1);
    if (v1) atomicOr(&viol[1], 1);
    if (v2) atomicOr(&viol[2], 1);
    __syncthreads();
    if (threadIdx.x == 0) {
        int t;
        if      (!viol[0]) t = 1;
        else if (!viol[1]) t = 2;
        else if (!viol[2]) t = 3;
        else               t = 0;
        g_mtype = t;
    }
}

__global__ __launch_bounds__(256) void mask_expand_kernel(
    const void* __restrict__ ue, const void* __restrict__ eu)
{
    int t = g_mtype;
    const void* src = blockIdx.z ? eu : ue;
    unsigned char* dst = blockIdx.z ? g_meu : g_mue;
    size_t stride = (size_t)gridDim.x * blockDim.x;
    for (size_t i = (size_t)blockIdx.x*blockDim.x + threadIdx.x;
         i < MASK_ELEMS; i += stride) {
        unsigned char v;
        if      (t == 1) v = ((const int*)src)[i] != 0;
        else if (t == 2) v = ((const float*)src)[i] != 0.f;
        else if (t == 3) v = ((const unsigned short*)src)[i] != 0;
        else             v = ((const unsigned char*)src)[i] != 0;
        dst[i] = v;
    }
}

// ===========================================================================
// bpp prep (unchanged)
// ===========================================================================
__global__ __launch_bounds__(256) void bpp_prep_kernel(
    const float* __restrict__ lb,
    const float* __restrict__ wp,
    const float* __restrict__ bp)
{
    __shared__ float t[32][33];
    int tx = threadIdx.x, ty = threadIdx.y;
    float w = wp[0], bb = bp[0];
    int x  = blockIdx.x*32 + tx;
    int y0 = blockIdx.y*32;
    #pragma unroll
    for (int i = ty; i < 32; i += 8) {
        float v = fmaf(w, lb[(size_t)(y0+i)*L_ + x], bb);
        g_bpp[(size_t)(y0+i)*L_ + x] = v;
        t[i][tx] = v;
    }
    __syncthreads();
    int xo = y0 + tx;
    #pragma unroll
    for (int i = ty; i < 32; i += 8) {
        g_bppT[(size_t)(blockIdx.x*32+i)*L_ + xo] = t[tx][i];
    }
}

// ===========================================================================
// mma.sync GEMM (bf16 hi/lo split): [8192 x 512] * [512 x 512] + bias.
//   Block tile 128(M) x 64(N), K chunks of 64, 256 threads (8 warps 4x2).
//   Warp tile 32x32 via m16n8k16: 2 M-tiles x 4 N-tiles x 3 products.
// SMEM layout (bf16, rows padded to 72 elems = 144 B, conflict-free ldmatrix):
//   A_hi [128][72] @0, A_lo @18432, B_hi(nxk) [64][72] @36864, B_lo @46080.
// ===========================================================================
#define AS_ 72
#define GM_A_HI 0
#define GM_A_LO 18432
#define GM_B_HI 36864
#define GM_B_LO 46080
#define GM_SMEM 55296

__global__ __launch_bounds__(256) void gemm_mma_kernel(
    const float* __restrict__ A0, const float* __restrict__ A1,
    const float* __restrict__ Wq, const float* __restrict__ Wk,
    const float* __restrict__ Wv,
    const float* __restrict__ bq, const float* __restrict__ bk,
    const float* __restrict__ bv,
    float* __restrict__ outp, int modebase)
{
    extern __shared__ __align__(16) unsigned char smem[];
    uint32_t sbase = smem_u32(smem);

    int tid = threadIdx.x;
    int wid = tid >> 5, lane = tid & 31;
    int wm = wid & 3, wn = wid >> 2;           // 4 warps M, 2 warps N

    int mode = modebase + blockIdx.z;
    const float* W; const float* bias; float* dst;
    if      (mode == 0) { W = Wq; bias = bq; dst = g_q; }
    else if (mode == 1) { W = Wk; bias = bk; dst = g_k; }
    else if (mode == 2) { W = Wv; bias = bv; dst = g_v; }
    else                { W = Wq; bias = bq; dst = outp; }

    const float* Abase0 = (modebase == 3) ? g_ctx : A0;
    const float* Abase1 = (modebase == 3) ? (g_ctx + (size_t)4096*D_) : A1;

    int n0   = blockIdx.x * 64;
    int row0 = blockIdx.y * 128;
    const float* A = (row0 < 4096) ? Abase0 : Abase1;
    int ar0 = (row0 < 4096) ? row0 : row0 - 4096;

    float acc[2][4][4];
    #pragma unroll
    for (int mi = 0; mi < 2; mi++)
        #pragma unroll
        for (int ni = 0; ni < 4; ni++)
            #pragma unroll
            for (int c = 0; c < 4; c++) acc[mi][ni][c] = 0.f;

    for (int kb = 0; kb < 8; kb++) {
        int kbase = kb * 64;
        __syncthreads();   // protect previous iteration's smem reads

        // ---- fill A: 128 rows x 64 k, hi/lo bf16 ----
        #pragma unroll
        for (int i = 0; i < 8; i++) {
            int idx = i*256 + tid;
            int row = idx >> 4, k0 = (idx & 15) * 4;
            float4 v = *(const float4*)&A[(size_t)(ar0+row)*D_ + kbase + k0];
            uint32_t h01, l01, h23, l23;
            split2(v.x, v.y, h01, l01);
            split2(v.z, v.w, h23, l23);
            uint32_t off = (uint32_t)(row*(AS_*2) + k0*2);
            *(uint32_t*)(smem + GM_A_HI + off)     = h01;
            *(uint32_t*)(smem + GM_A_HI + off + 4) = h23;
            *(uint32_t*)(smem + GM_A_LO + off)     = l01;
            *(uint32_t*)(smem + GM_A_LO + off + 4) = l23;
        }
        // ---- fill B transposed: Bt[n][k], 64 x 64 ----
        #pragma unroll
        for (int i = 0; i < 4; i++) {
            int idx = i*256 + tid;
            int kk = idx >> 4, nf = (idx & 15) * 4;
            float4 v = *(const float4*)&W[(size_t)(kbase+kk)*D_ + n0 + nf];
            float xs[4] = {v.x, v.y, v.z, v.w};
            #pragma unroll
            for (int j = 0; j < 4; j++) {
                unsigned short h = f2bf_bits(xs[j]);
                unsigned short l = f2bf_bits(xs[j] - bfbits2f(h));
                uint32_t off = (uint32_t)((nf+j)*(AS_*2) + kk*2);
                *(unsigned short*)(smem + GM_B_HI + off) = h;
                *(unsigned short*)(smem + GM_B_LO + off) = l;
            }
        }
        __syncthreads();

        // ---- mma over 4 k-steps of 16 ----
        #pragma unroll
        for (int ks = 0; ks < 4; ks++) {
            uint32_t a_hi[2][4], a_lo[2][4], b_hi[8], b_lo[8];
            // A frags (16x16 tiles): lanes 0-15 rows, lanes 16-31 k+8 half
            #pragma unroll
            for (int mi = 0; mi < 2; mi++) {
                int row = wm*32 + mi*16 + (lane & 15);
                int kcol = ks*16 + ((lane >> 4) << 3);
                uint32_t off = (uint32_t)(row*(AS_*2) + kcol*2);
                ldsm_x4(a_hi[mi][0], a_hi[mi][1], a_hi[mi][2], a_hi[mi][3],
                        sbase + GM_A_HI + off);
                ldsm_x4(a_lo[mi][0], a_lo[mi][1], a_lo[mi][2], a_lo[mi][3],
                        sbase + GM_A_LO + off);
            }
            // B frags: x4 covers two n8-tiles (16 n-rows), need 2 groups
            #pragma unroll
            for (int g = 0; g < 2; g++) {
                int r  = lane & 7;
                int hk = (lane >> 3) & 1;
                int hn = (lane >> 4) & 1;
                int nrow = wn*32 + g*16 + hn*8 + r;
                int kcol = ks*16 + hk*8;
                uint32_t off = (uint32_t)(nrow*(AS_*2) + kcol*2);
                ldsm_x4(b_hi[g*4+0], b_hi[g*4+1], b_hi[g*4+2], b_hi[g*4+3],
                        sbase + GM_B_HI + off);
                ldsm_x4(b_lo[g*4+0], b_lo[g*4+1], b_lo[g*4+2], b_lo[g*4+3],
                        sbase + GM_B_LO + off);
            }
            #pragma unroll
            for (int mi = 0; mi < 2; mi++) {
                #pragma unroll
                for (int ni = 0; ni < 4; ni++) {
                    mma_bf16(acc[mi][ni], a_hi[mi], &b_hi[ni*2]);
                    mma_bf16(acc[mi][ni], a_lo[mi], &b_hi[ni*2]);
                    mma_bf16(acc[mi][ni], a_hi[mi], &b_lo[ni*2]);
                }
            }
        }
    }

    // ---- epilogue ----
    float scale = (mode == 0) ? 0.125f : 1.f;
    #pragma unroll
    for (int mi = 0; mi < 2; mi++) {
        #pragma unroll
        for (int ni = 0; ni < 4; ni++) {
            int nl = wn*32 + ni*8 + (lane & 3)*2;
            float b0 = bias[n0 + nl], b1 = bias[n0 + nl + 1];
            #pragma unroll
            for (int half = 0; half < 2; half++) {
                int m = row0 + wm*32 + mi*16 + (lane >> 2) + half*8;
                float2 o;
                o.x = (acc[mi][ni][half*2+0] + b0) * scale;
                o.y = (acc[mi][ni][half*2+1] + b1) * scale;
                if (mode < 3) {
                    int enc = m >> 12, b = (m >> 10) & 3, l = m & 1023;
                    int h = n0 >> 6;
                    size_t idx = ((((size_t)(enc*B_ + b))*H_ + h)*L_ + l)*HD_ + nl;
                    *(float2*)&dst[idx] = o;
                } else {
                    *(float2*)&dst[(size_t)m*D_ + n0 + nl] = o;
                }
            }
        }
    }
}

// ===========================================================================
// Fused flash attention (fp32, unchanged)
// ===========================================================================
__global__ __launch_bounds__(256) void attn_kernel()
{
    extern __shared__ float sm[];
    float* q_s = sm;
    float* k_s = sm + 64*65;
    float* v_s = sm + 2*64*65;
    float* p_s = sm + 3*64*65;

    int tid = threadIdx.x, tx = tid & 15, ty = tid >> 4;
    int qt = blockIdx.x, bh = blockIdx.y, dir = blockIdx.z;
    int b = bh >> 3, h = bh & 7;
    int enc_q = dir, enc_kv = 1 - dir;

    const float* Qg = g_q + ((size_t)((enc_q *B_ + b)*H_ + h))*L_*HD_;
    const float* Kg = g_k + ((size_t)((enc_kv*B_ + b)*H_ + h))*L_*HD_;
    const float* Vg = g_v + ((size_t)((enc_kv*B_ + b)*H_ + h))*L_*HD_;
    const unsigned char* Mk = (dir == 0 ? g_mue : g_meu) + (size_t)b*L_*L_;
    const float* Bp = (dir == 0) ? g_bpp : g_bppT;
    int q0 = qt * 64;

    #pragma unroll
    for (int i = 0; i < 16; i++) {
        int e = i*256 + tid;
        int r = e >> 6, hd = e & 63;
        q_s[hd*65 + r] = Qg[(size_t)(q0+r)*64 + hd];
    }

    float o[4][4];
    float mreg[4], lreg[4];
    #pragma unroll
    for (int i = 0; i < 4; i++) {
        mreg[i] = -3.0e38f; lreg[i] = 0.f;
        #pragma unroll
        for (int j = 0; j < 4; j++) o[i][j] = 0.f;
    }

    for (int t = 0; t < 16; t++) {
        int k0 = t * 64;
        __syncthreads();
        #pragma unroll
        for (int i = 0; i < 16; i++) {
            int e = i*256 + tid;
            int r = e >> 6, hd = e & 63;
            k_s[hd*65 + r] = Kg[(size_t)(k0+r)*64 + hd];
            v_s[r*65 + hd] = Vg[(size_t)(k0+r)*64 + hd];
        }
        __syncthreads();

        float s[4][4];
        #pragma unroll
        for (int i = 0; i < 4; i++)
            #pragma unroll
            for (int j = 0; j < 4; j++) s[i][j] = 0.f;

        #pragma unroll 8
        for (int kk = 0; kk < 64; kk++) {
            float qv[4], kv[4];
            #pragma unroll
            for (int i = 0; i < 4; i++) qv[i] = q_s[kk*65 + ty*4 + i];
            #pragma unroll
            for (int j = 0; j < 4; j++) kv[j] = k_s[kk*65 + tx*4 + j];
            #pragma unroll
            for (int i = 0; i < 4; i++)
                #pragma unroll
                for (int j = 0; j < 4; j++)
                    s[i][j] = fmaf(qv[i], kv[j], s[i][j]);
        }

        #pragma unroll
        for (int i = 0; i < 4; i++) {
            int qg = q0 + ty*4 + i;
            const float*         bprow = Bp + (size_t)qg*L_ + k0 + tx*4;
            const unsigned char* mrow  = Mk + (size_t)qg*L_ + k0 + tx*4;
            #pragma unroll
            for (int j = 0; j < 4; j++) {
                float sv = s[i][j] + bprow[j];
                s[i][j] = mrow[j] ? sv : -3.0e38f;
            }
        }

        #pragma unroll
        for (int i = 0; i < 4; i++) {
            float mx = fmaxf(fmaxf(s[i][0], s[i][1]), fmaxf(s[i][2], s[i][3]));
            mx = fmaxf(mx, __shfl_xor_sync(0xffffffffu, mx, 8));
            mx = fmaxf(mx, __shfl_xor_sync(0xffffffffu, mx, 4));
            mx = fmaxf(mx, __shfl_xor_sync(0xffffffffu, mx, 2));
            mx = fmaxf(mx, __shfl_xor_sync(0xffffffffu, mx, 1));
            float mnew = fmaxf(mreg[i], mx);
            float corr = __expf(mreg[i] - mnew);
            float p0 = __expf(s[i][0] - mnew);
            float p1 = __expf(s[i][1] - mnew);
            float p2 = __expf(s[i][2] - mnew);
            float p3 = __expf(s[i][3] - mnew);
            float rs = (p0 + p1) + (p2 + p3);
            rs += __shfl_xor_sync(0xffffffffu, rs, 8);
            rs += __shfl_xor_sync(0xffffffffu, rs, 4);
            rs += __shfl_xor_sync(0xffffffffu, rs, 2);
            rs += __shfl_xor_sync(0xffffffffu, rs, 1);
            lreg[i] = lreg[i]*corr + rs;
            mreg[i] = mnew;
            #pragma unroll
            for (int j = 0; j < 4; j++) o[i][j] *= corr;
            int pr = (ty*4 + i)*65 + tx*4;
            p_s[pr+0] = p0; p_s[pr+1] = p1; p_s[pr+2] = p2; p_s[pr+3] = p3;
        }
        __syncthreads();

        #pragma unroll 8
        for (int kk = 0; kk < 64; kk++) {
            float pv[4], vv[4];
            #pragma unroll
            for (int i = 0; i < 4; i++) pv[i] = p_s[(ty*4+i)*65 + kk];
            #pragma unroll
            for (int j = 0; j < 4; j++) vv[j] = v_s[kk*65 + tx*4 + j];
            #pragma unroll
            for (int i = 0; i < 4; i++)
                #pragma unroll
                for (int j = 0; j < 4; j++)
                    o[i][j] = fmaf(pv[i], vv[j], o[i][j]);
        }
    }

    #pragma unroll
    for (int i = 0; i < 4; i++) {
        float inv = 1.f / lreg[i];
        float4 ov;
        ov.x = o[i][0]*inv; ov.y = o[i][1]*inv;
        ov.z = o[i][2]*inv; ov.w = o[i][3]*inv;
        size_t idx = ((size_t)((enc_q*B_ + b))*L_ + q0 + ty*4 + i)*D_
                     + h*64 + tx*4;
        *(float4*)&g_ctx[idx] = ov;
    }
}

// ---------------------------------------------------------------------------
extern "C" void kernel_launch(void* const* d_in, const int* in_sizes, int n_in,
                              void* d_out, int out_size)
{
    const float* u_enc     = (const float*)d_in[0];
    const float* e_enc     = (const float*)d_in[1];
    const float* logit_bpp = (const float*)d_in[2];
    const void*  ue_mask   = d_in[3];
    const void*  eu_mask   = d_in[4];
    const float* wq_k = (const float*)d_in[5];
    const float* wq_b = (const float*)d_in[6];
    const float* wk_k = (const float*)d_in[7];
    const float* wk_b = (const float*)d_in[8];
    const float* wv_k = (const float*)d_in[9];
    const float* wv_b = (const float*)d_in[10];
    const float* wo_k = (const float*)d_in[11];
    const float* wo_b = (const float*)d_in[12];
    const float* bpp_w = (const float*)d_in[13];
    const float* bpp_b = (const float*)d_in[14];
    float* out = (float*)d_out;

    const int ATTN_SMEM = 4*64*65*sizeof(float);   // 66,560 B
    cudaFuncSetAttribute((const void*)attn_kernel,
                         cudaFuncAttributeMaxDynamicSharedMemorySize, ATTN_SMEM);
    cudaFuncSetAttribute((const void*)gemm_mma_kernel,
                         cudaFuncAttributeMaxDynamicSharedMemorySize, GM_SMEM);

    // 0) mask dtype detection + expansion to uint8
    mask_detect_kernel<<<1, 256>>>((const unsigned int*)ue_mask);
    mask_expand_kernel<<<dim3(4096, 1, 2), 256>>>(ue_mask, eu_mask);
    // 1) fused QKV projections on tensor pipe (z: 0=q,1=k,2=v)
    gemm_mma_kernel<<<dim3(8, 64, 3), 256, GM_SMEM>>>(u_enc, e_enc,
                                                      wq_k, wk_k, wv_k,
                                                      wq_b, wk_b, wv_b,
                                                      nullptr, 0);
    // 2) bias prep
    bpp_prep_kernel<<<dim3(32, 32), dim3(32, 8)>>>(logit_bpp, bpp_w, bpp_b);
    // 3) fused attention, both directions
    attn_kernel<<<dim3(16, 32, 2), 256, ATTN_SMEM>>>();
    // 4) output projection on tensor pipe -> d_out
    gemm_mma_kernel<<<dim3(8, 64, 1), 256, GM_SMEM>>>(nullptr, nullptr,
                                                      wo_k, nullptr, nullptr,
                                                      wo_b, nullptr, nullptr,
                                                      out, 3);
}

// round 5
// speedup vs baseline: 1.7233x; 1.4615x over previous
#include <cuda_runtime.h>
#include <cuda_bf16.h>
#include <math.h>
#include <float.h>
#include <stdint.h>
#include <string.h>

#define B_  4
#define L_  1024
#define D_  512
#define H_  8
#define HD_ 64
#define PROJ_ELEMS (2*B_*H_*L_*HD_)   /* 4,194,304 */
#define MASK_ELEMS ((size_t)B_*L_*L_) /* 4,194,304 */

__device__ float g_q[PROJ_ELEMS];
__device__ float g_k[PROJ_ELEMS];
__device__ float g_v[PROJ_ELEMS];
__device__ float g_ctx[PROJ_ELEMS];
__device__ float g_bpp[L_*L_];
__device__ float g_bppT[L_*L_];
__device__ unsigned char g_mue[B_*L_*L_];
__device__ unsigned char g_meu[B_*L_*L_];
__device__ int g_mtype;

// ===========================================================================
// mma.sync helpers (base PTX — compute_103 virtual arch has no tcgen05)
// ===========================================================================
__device__ __forceinline__ uint32_t smem_u32(const void* p) {
    uint32_t a;
    asm("{ .reg .u64 t; cvta.to.shared.u64 t, %1; cvt.u32.u64 %0, t; }"
        : "=r"(a) : "l"(p));
    return a;
}
__device__ __forceinline__ void ldsm_x4(uint32_t& r0, uint32_t& r1,
                                        uint32_t& r2, uint32_t& r3,
                                        uint32_t addr) {
    asm volatile("ldmatrix.sync.aligned.m8n8.x4.shared.b16 {%0,%1,%2,%3}, [%4];"
                 : "=r"(r0), "=r"(r1), "=r"(r2), "=r"(r3) : "r"(addr));
}
__device__ __forceinline__ void ldsm_x4_t(uint32_t& r0, uint32_t& r1,
                                          uint32_t& r2, uint32_t& r3,
                                          uint32_t addr) {
    asm volatile("ldmatrix.sync.aligned.m8n8.x4.trans.shared.b16 {%0,%1,%2,%3}, [%4];"
                 : "=r"(r0), "=r"(r1), "=r"(r2), "=r"(r3) : "r"(addr));
}
__device__ __forceinline__ void mma_bf16(float* c, const uint32_t* a,
                                         const uint32_t* b) {
    asm volatile("mma.sync.aligned.m16n8k16.row.col.f32.bf16.bf16.f32 "
                 "{%0,%1,%2,%3}, {%4,%5,%6,%7}, {%8,%9}, {%0,%1,%2,%3};"
                 : "+f"(c[0]), "+f"(c[1]), "+f"(c[2]), "+f"(c[3])
                 : "r"(a[0]), "r"(a[1]), "r"(a[2]), "r"(a[3]),
                   "r"(b[0]), "r"(b[1]));
}
__device__ __forceinline__ unsigned short f2bf_bits(float x) {
    __nv_bfloat16 h = __float2bfloat16(x);
    unsigned short u; memcpy(&u, &h, 2); return u;
}
__device__ __forceinline__ float bfbits2f(unsigned short u) {
    __nv_bfloat16 h; memcpy(&h, &u, 2); return __bfloat162float(h);
}
// pack hi pair + lo pair from two floats
__device__ __forceinline__ void split2(float x, float y, uint32_t& hi, uint32_t& lo) {
    unsigned short hx = f2bf_bits(x), hy = f2bf_bits(y);
    unsigned short lx = f2bf_bits(x - bfbits2f(hx));
    unsigned short ly = f2bf_bits(y - bfbits2f(hy));
    hi = (uint32_t)hx | ((uint32_t)hy << 16);
    lo = (uint32_t)lx | ((uint32_t)ly << 16);
}

// ===========================================================================
// Mask dtype detect + expand (unchanged)
// ===========================================================================
__global__ void mask_detect_kernel(const unsigned int* __restrict__ m)
{
    __shared__ int viol[3];
    if (threadIdx.x < 3) viol[threadIdx.x] = 0;
    __syncthreads();
    int v0 = 0, v1 = 0, v2 = 0;
    for (int i = threadIdx.x; i < 16384; i += 256) {
        unsigned w = m[i];
        if (w > 1u) v0 = 1;
        if (w != 0u && w != 0x3F800000u) v1 = 1;
        if (w != 0u && w != 0x3F800000u && w != 0x00003F80u && w != 0x3F803F80u) v2 = 1;
    }
    if (v0) atomicOr(&viol[0], 1);
    if (v1) atomicOr(&viol[1], 1);
    if (v2) atomicOr(&viol[2], 1);
    __syncthreads();
    if (threadIdx.x == 0) {
        int t;
        if      (!viol[0]) t = 1;
        else if (!viol[1]) t = 2;
        else if (!viol[2]) t = 3;
        else               t = 0;
        g_mtype = t;
    }
}

__global__ __launch_bounds__(256) void mask_expand_kernel(
    const void* __restrict__ ue, const void* __restrict__ eu)
{
    int t = g_mtype;
    const void* src = blockIdx.z ? eu : ue;
    unsigned char* dst = blockIdx.z ? g_meu : g_mue;
    size_t stride = (size_t)gridDim.x * blockDim.x;
    for (size_t i = (size_t)blockIdx.x*blockDim.x + threadIdx.x;
         i < MASK_ELEMS; i += stride) {
        unsigned char v;
        if      (t == 1) v = ((const int*)src)[i] != 0;
        else if (t == 2) v = ((const float*)src)[i] != 0.f;
        else if (t == 3) v = ((const unsigned short*)src)[i] != 0;
        else             v = ((const unsigned char*)src)[i] != 0;
        dst[i] = v;
    }
}

// ===========================================================================
// bpp prep (unchanged)
// ===========================================================================
__global__ __launch_bounds__(256) void bpp_prep_kernel(
    const float* __restrict__ lb,
    const float* __restrict__ wp,
    const float* __restrict__ bp)
{
    __shared__ float t[32][33];
    int tx = threadIdx.x, ty = threadIdx.y;
    float w = wp[0], bb = bp[0];
    int x  = blockIdx.x*32 + tx;
    int y0 = blockIdx.y*32;
    #pragma unroll
    for (int i = ty; i < 32; i += 8) {
        float v = fmaf(w, lb[(size_t)(y0+i)*L_ + x], bb);
        g_bpp[(size_t)(y0+i)*L_ + x] = v;
        t[i][tx] = v;
    }
    __syncthreads();
    int xo = y0 + tx;
    #pragma unroll
    for (int i = ty; i < 32; i += 8) {
        g_bppT[(size_t)(blockIdx.x*32+i)*L_ + xo] = t[tx][i];
    }
}

// ===========================================================================
// mma.sync GEMM (bf16 hi/lo split) — unchanged from Round 4
// ===========================================================================
#define AS_ 72
#define GM_A_HI 0
#define GM_A_LO 18432
#define GM_B_HI 36864
#define GM_B_LO 46080
#define GM_SMEM 55296

__global__ __launch_bounds__(256) void gemm_mma_kernel(
    const float* __restrict__ A0, const float* __restrict__ A1,
    const float* __restrict__ Wq, const float* __restrict__ Wk,
    const float* __restrict__ Wv,
    const float* __restrict__ bq, const float* __restrict__ bk,
    const float* __restrict__ bv,
    float* __restrict__ outp, int modebase)
{
    extern __shared__ __align__(16) unsigned char smem[];
    uint32_t sbase = smem_u32(smem);

    int tid = threadIdx.x;
    int wid = tid >> 5, lane = tid & 31;
    int wm = wid & 3, wn = wid >> 2;

    int mode = modebase + blockIdx.z;
    const float* W; const float* bias; float* dst;
    if      (mode == 0) { W = Wq; bias = bq; dst = g_q; }
    else if (mode == 1) { W = Wk; bias = bk; dst = g_k; }
    else if (mode == 2) { W = Wv; bias = bv; dst = g_v; }
    else                { W = Wq; bias = bq; dst = outp; }

    const float* Abase0 = (modebase == 3) ? g_ctx : A0;
    const float* Abase1 = (modebase == 3) ? (g_ctx + (size_t)4096*D_) : A1;

    int n0   = blockIdx.x * 64;
    int row0 = blockIdx.y * 128;
    const float* A = (row0 < 4096) ? Abase0 : Abase1;
    int ar0 = (row0 < 4096) ? row0 : row0 - 4096;

    float acc[2][4][4];
    #pragma unroll
    for (int mi = 0; mi < 2; mi++)
        #pragma unroll
        for (int ni = 0; ni < 4; ni++)
            #pragma unroll
            for (int c = 0; c < 4; c++) acc[mi][ni][c] = 0.f;

    for (int kb = 0; kb < 8; kb++) {
        int kbase = kb * 64;
        __syncthreads();

        #pragma unroll
        for (int i = 0; i < 8; i++) {
            int idx = i*256 + tid;
            int row = idx >> 4, k0 = (idx & 15) * 4;
            float4 v = *(const float4*)&A[(size_t)(ar0+row)*D_ + kbase + k0];
            uint32_t h01, l01, h23, l23;
            split2(v.x, v.y, h01, l01);
            split2(v.z, v.w, h23, l23);
            uint32_t off = (uint32_t)(row*(AS_*2) + k0*2);
            *(uint32_t*)(smem + GM_A_HI + off)     = h01;
            *(uint32_t*)(smem + GM_A_HI + off + 4) = h23;
            *(uint32_t*)(smem + GM_A_LO + off)     = l01;
            *(uint32_t*)(smem + GM_A_LO + off + 4) = l23;
        }
        #pragma unroll
        for (int i = 0; i < 4; i++) {
            int idx = i*256 + tid;
            int kk = idx >> 4, nf = (idx & 15) * 4;
            float4 v = *(const float4*)&W[(size_t)(kbase+kk)*D_ + n0 + nf];
            float xs[4] = {v.x, v.y, v.z, v.w};
            #pragma unroll
            for (int j = 0; j < 4; j++) {
                unsigned short h = f2bf_bits(xs[j]);
                unsigned short l = f2bf_bits(xs[j] - bfbits2f(h));
                uint32_t off = (uint32_t)((nf+j)*(AS_*2) + kk*2);
                *(unsigned short*)(smem + GM_B_HI + off) = h;
                *(unsigned short*)(smem + GM_B_LO + off) = l;
            }
        }
        __syncthreads();

        #pragma unroll
        for (int ks = 0; ks < 4; ks++) {
            uint32_t a_hi[2][4], a_lo[2][4], b_hi[8], b_lo[8];
            #pragma unroll
            for (int mi = 0; mi < 2; mi++) {
                int row = wm*32 + mi*16 + (lane & 15);
                int kcol = ks*16 + ((lane >> 4) << 3);
                uint32_t off = (uint32_t)(row*(AS_*2) + kcol*2);
                ldsm_x4(a_hi[mi][0], a_hi[mi][1], a_hi[mi][2], a_hi[mi][3],
                        sbase + GM_A_HI + off);
                ldsm_x4(a_lo[mi][0], a_lo[mi][1], a_lo[mi][2], a_lo[mi][3],
                        sbase + GM_A_LO + off);
            }
            #pragma unroll
            for (int g = 0; g < 2; g++) {
                int r  = lane & 7;
                int hk = (lane >> 3) & 1;
                int hn = (lane >> 4) & 1;
                int nrow = wn*32 + g*16 + hn*8 + r;
                int kcol = ks*16 + hk*8;
                uint32_t off = (uint32_t)(nrow*(AS_*2) + kcol*2);
                ldsm_x4(b_hi[g*4+0], b_hi[g*4+1], b_hi[g*4+2], b_hi[g*4+3],
                        sbase + GM_B_HI + off);
                ldsm_x4(b_lo[g*4+0], b_lo[g*4+1], b_lo[g*4+2], b_lo[g*4+3],
                        sbase + GM_B_LO + off);
            }
            #pragma unroll
            for (int mi = 0; mi < 2; mi++) {
                #pragma unroll
                for (int ni = 0; ni < 4; ni++) {
                    mma_bf16(acc[mi][ni], a_hi[mi], &b_hi[ni*2]);
                    mma_bf16(acc[mi][ni], a_lo[mi], &b_hi[ni*2]);
                    mma_bf16(acc[mi][ni], a_hi[mi], &b_lo[ni*2]);
                }
            }
        }
    }

    float scale = (mode == 0) ? 0.125f : 1.f;
    #pragma unroll
    for (int mi = 0; mi < 2; mi++) {
        #pragma unroll
        for (int ni = 0; ni < 4; ni++) {
            int nl = wn*32 + ni*8 + (lane & 3)*2;
            float b0 = bias[n0 + nl], b1 = bias[n0 + nl + 1];
            #pragma unroll
            for (int half = 0; half < 2; half++) {
                int m = row0 + wm*32 + mi*16 + (lane >> 2) + half*8;
                float2 o;
                o.x = (acc[mi][ni][half*2+0] + b0) * scale;
                o.y = (acc[mi][ni][half*2+1] + b1) * scale;
                if (mode < 3) {
                    int enc = m >> 12, b = (m >> 10) & 3, l = m & 1023;
                    int h = n0 >> 6;
                    size_t idx = ((((size_t)(enc*B_ + b))*H_ + h)*L_ + l)*HD_ + nl;
                    *(float2*)&dst[idx] = o;
                } else {
                    *(float2*)&dst[(size_t)m*D_ + n0 + nl] = o;
                }
            }
        }
    }
}

// ===========================================================================
// Flash attention on mma.sync (bf16 hi/lo split).
//   grid (16 qtiles, 32 b*h, 2 dirs), 128 threads (4 warps).
//   Warp w handles q rows [w*16, w*16+16). Per 64-key tile:
//   S(16x64) via 3-product split MMA; softmax in accumulator regs;
//   P fed to PV MMA directly from registers (acc layout == A-frag layout).
// SMEM (pad rows to 72 bf16 = 144B): QH 0, QL 9216, KH 18432, KL 27648,
//   VH 36864, VL 46080; total 55296.
// ===========================================================================
#define AT_QH 0
#define AT_QL 9216
#define AT_KH 18432
#define AT_KL 27648
#define AT_VH 36864
#define AT_VL 46080
#define AT_SMEM 55296

__global__ __launch_bounds__(128) void attn_mma_kernel()
{
    extern __shared__ __align__(16) unsigned char smem[];
    uint32_t sbase = smem_u32(smem);

    int tid = threadIdx.x;
    int wid = tid >> 5, lane = tid & 31;
    int r = lane >> 2, cq = lane & 3;

    int qt = blockIdx.x, bh = blockIdx.y, dir = blockIdx.z;
    int b = bh >> 3, h = bh & 7;
    int enc_q = dir, enc_kv = 1 - dir;

    const float* Qg = g_q + ((size_t)((enc_q *B_ + b)*H_ + h))*L_*HD_;
    const float* Kg = g_k + ((size_t)((enc_kv*B_ + b)*H_ + h))*L_*HD_;
    const float* Vg = g_v + ((size_t)((enc_kv*B_ + b)*H_ + h))*L_*HD_;
    const unsigned char* Mk = (dir == 0 ? g_mue : g_meu) + (size_t)b*L_*L_;
    const float* Bp = (dir == 0) ? g_bpp : g_bppT;
    int q0 = qt * 64;

    // ---- load Q tile (64x64) hi/lo into smem ----
    #pragma unroll
    for (int i = 0; i < 8; i++) {
        int idx = i*128 + tid;
        int row = idx >> 4, k4 = (idx & 15) * 4;
        float4 v = *(const float4*)&Qg[(size_t)(q0+row)*HD_ + k4];
        uint32_t h01, l01, h23, l23;
        split2(v.x, v.y, h01, l01);
        split2(v.z, v.w, h23, l23);
        uint32_t off = (uint32_t)(row*(AS_*2) + k4*2);
        *(uint32_t*)(smem + AT_QH + off)     = h01;
        *(uint32_t*)(smem + AT_QH + off + 4) = h23;
        *(uint32_t*)(smem + AT_QL + off)     = l01;
        *(uint32_t*)(smem + AT_QL + off + 4) = l23;
    }
    __syncthreads();

    // ---- Q A-fragments, resident in regs for whole kernel ----
    uint32_t aq_h[4][4], aq_l[4][4];
    #pragma unroll
    for (int ks = 0; ks < 4; ks++) {
        int row = wid*16 + (lane & 15);
        int kcol = ks*16 + ((lane >> 4) << 3);
        uint32_t off = (uint32_t)(row*(AS_*2) + kcol*2);
        ldsm_x4(aq_h[ks][0], aq_h[ks][1], aq_h[ks][2], aq_h[ks][3], sbase + AT_QH + off);
        ldsm_x4(aq_l[ks][0], aq_l[ks][1], aq_l[ks][2], aq_l[ks][3], sbase + AT_QL + off);
    }

    float o_acc[8][4];
    #pragma unroll
    for (int nt = 0; nt < 8; nt++)
        #pragma unroll
        for (int c = 0; c < 4; c++) o_acc[nt][c] = 0.f;
    float m0r = -3.0e38f, m1r = -3.0e38f, l0r = 0.f, l1r = 0.f;

    int qg0 = q0 + wid*16 + r;
    int qg1 = qg0 + 8;
    const float* bp0base = Bp + (size_t)qg0*L_ + cq*2;
    const float* bp1base = Bp + (size_t)qg1*L_ + cq*2;
    const unsigned char* mp0base = Mk + (size_t)qg0*L_ + cq*2;
    const unsigned char* mp1base = Mk + (size_t)qg1*L_ + cq*2;

    for (int t = 0; t < 16; t++) {
        int k0 = t * 64;
        __syncthreads();   // all warps finished reading prev K/V tiles

        // ---- fill K and V tiles (64 keys x 64 hd) hi/lo ----
        #pragma unroll
        for (int i = 0; i < 8; i++) {
            int idx = i*128 + tid;
            int key = idx >> 4, h4 = (idx & 15) * 4;
            uint32_t off = (uint32_t)(key*(AS_*2) + h4*2);
            float4 kv = *(const float4*)&Kg[(size_t)(k0+key)*HD_ + h4];
            uint32_t h01, l01, h23, l23;
            split2(kv.x, kv.y, h01, l01);
            split2(kv.z, kv.w, h23, l23);
            *(uint32_t*)(smem + AT_KH + off)     = h01;
            *(uint32_t*)(smem + AT_KH + off + 4) = h23;
            *(uint32_t*)(smem + AT_KL + off)     = l01;
            *(uint32_t*)(smem + AT_KL + off + 4) = l23;
            float4 vv = *(const float4*)&Vg[(size_t)(k0+key)*HD_ + h4];
            split2(vv.x, vv.y, h01, l01);
            split2(vv.z, vv.w, h23, l23);
            *(uint32_t*)(smem + AT_VH + off)     = h01;
            *(uint32_t*)(smem + AT_VH + off + 4) = h23;
            *(uint32_t*)(smem + AT_VL + off)     = l01;
            *(uint32_t*)(smem + AT_VL + off + 4) = l23;
        }
        __syncthreads();

        // ---- S = Q K^T (16 x 64 per warp), 3-product split ----
        float s_acc[8][4];
        #pragma unroll
        for (int nt = 0; nt < 8; nt++)
            #pragma unroll
            for (int c = 0; c < 4; c++) s_acc[nt][c] = 0.f;

        #pragma unroll
        for (int ks = 0; ks < 4; ks++) {
            #pragma unroll
            for (int g = 0; g < 4; g++) {
                uint32_t bk_h[4], bk_l[4];
                int rr = lane & 7;
                int hk = (lane >> 3) & 1;
                int hn = (lane >> 4) & 1;
                int nrow = g*16 + hn*8 + rr;
                int kcol = ks*16 + hk*8;
                uint32_t off = (uint32_t)(nrow*(AS_*2) + kcol*2);
                ldsm_x4(bk_h[0], bk_h[1], bk_h[2], bk_h[3], sbase + AT_KH + off);
                ldsm_x4(bk_l[0], bk_l[1], bk_l[2], bk_l[3], sbase + AT_KL + off);
                #pragma unroll
                for (int sub = 0; sub < 2; sub++) {
                    int nt = g*2 + sub;
                    mma_bf16(s_acc[nt], aq_h[ks], &bk_h[sub*2]);
                    mma_bf16(s_acc[nt], aq_l[ks], &bk_h[sub*2]);
                    mma_bf16(s_acc[nt], aq_h[ks], &bk_l[sub*2]);
                }
            }
        }

        // ---- bias + mask ----
        #pragma unroll
        for (int nt = 0; nt < 8; nt++) {
            int cc = k0 + nt*8;
            float2 b0v = *(const float2*)&bp0base[cc];
            float2 b1v = *(const float2*)&bp1base[cc];
            uchar2 m0v = *(const uchar2*)&mp0base[cc];
            uchar2 m1v = *(const uchar2*)&mp1base[cc];
            s_acc[nt][0] = m0v.x ? s_acc[nt][0] + b0v.x : -3.0e38f;
            s_acc[nt][1] = m0v.y ? s_acc[nt][1] + b0v.y : -3.0e38f;
            s_acc[nt][2] = m1v.x ? s_acc[nt][2] + b1v.x : -3.0e38f;
            s_acc[nt][3] = m1v.y ? s_acc[nt][3] + b1v.y : -3.0e38f;
        }

        // ---- online softmax (rows qg0, qg1; quad-lane reduction) ----
        float mx0 = -3.0e38f, mx1 = -3.0e38f;
        #pragma unroll
        for (int nt = 0; nt < 8; nt++) {
            mx0 = fmaxf(mx0, fmaxf(s_acc[nt][0], s_acc[nt][1]));
            mx1 = fmaxf(mx1, fmaxf(s_acc[nt][2], s_acc[nt][3]));
        }
        mx0 = fmaxf(mx0, __shfl_xor_sync(0xffffffffu, mx0, 1));
        mx0 = fmaxf(mx0, __shfl_xor_sync(0xffffffffu, mx0, 2));
        mx1 = fmaxf(mx1, __shfl_xor_sync(0xffffffffu, mx1, 1));
        mx1 = fmaxf(mx1, __shfl_xor_sync(0xffffffffu, mx1, 2));

        float mn0 = fmaxf(m0r, mx0);
        float mn1 = fmaxf(m1r, mx1);
        float c0 = __expf(m0r - mn0);
        float c1 = __expf(m1r - mn1);
        m0r = mn0; m1r = mn1;

        float rs0 = 0.f, rs1 = 0.f;
        #pragma unroll
        for (int nt = 0; nt < 8; nt++) {
            s_acc[nt][0] = __expf(s_acc[nt][0] - m0r); rs0 += s_acc[nt][0];
            s_acc[nt][1] = __expf(s_acc[nt][1] - m0r); rs0 += s_acc[nt][1];
            s_acc[nt][2] = __expf(s_acc[nt][2] - m1r); rs1 += s_acc[nt][2];
            s_acc[nt][3] = __expf(s_acc[nt][3] - m1r); rs1 += s_acc[nt][3];
        }
        rs0 += __shfl_xor_sync(0xffffffffu, rs0, 1);
        rs0 += __shfl_xor_sync(0xffffffffu, rs0, 2);
        rs1 += __shfl_xor_sync(0xffffffffu, rs1, 1);
        rs1 += __shfl_xor_sync(0xffffffffu, rs1, 2);
        l0r = l0r*c0 + rs0;
        l1r = l1r*c1 + rs1;

        #pragma unroll
        for (int nt = 0; nt < 8; nt++) {
            o_acc[nt][0] *= c0; o_acc[nt][1] *= c0;
            o_acc[nt][2] *= c1; o_acc[nt][3] *= c1;
        }

        // ---- O += P V : P from regs (acc layout == A-frag layout) ----
        #pragma unroll
        for (int ks = 0; ks < 4; ks++) {
            int t0 = 2*ks, t1 = 2*ks + 1;
            uint32_t ap_h[4], ap_l[4];
            split2(s_acc[t0][0], s_acc[t0][1], ap_h[0], ap_l[0]);
            split2(s_acc[t0][2], s_acc[t0][3], ap_h[1], ap_l[1]);
            split2(s_acc[t1][0], s_acc[t1][1], ap_h[2], ap_l[2]);
            split2(s_acc[t1][2], s_acc[t1][3], ap_h[3], ap_l[3]);
            #pragma unroll
            for (int g = 0; g < 4; g++) {
                uint32_t bv_h[4], bv_l[4];
                int kk  = ks*16 + ((lane >> 3) & 1)*8 + (lane & 7);
                int hdo = g*16 + ((lane >> 4) & 1)*8;
                uint32_t off = (uint32_t)(kk*(AS_*2) + hdo*2);
                ldsm_x4_t(bv_h[0], bv_h[1], bv_h[2], bv_h[3], sbase + AT_VH + off);
                ldsm_x4_t(bv_l[0], bv_l[1], bv_l[2], bv_l[3], sbase + AT_VL + off);
                #pragma unroll
                for (int sub = 0; sub < 2; sub++) {
                    int nt = g*2 + sub;
                    mma_bf16(o_acc[nt], ap_h, &bv_h[sub*2]);
                    mma_bf16(o_acc[nt], ap_l, &bv_h[sub*2]);
                    mma_bf16(o_acc[nt], ap_h, &bv_l[sub*2]);
                }
            }
        }
    }

    // ---- finalize: divide by l, write ctx[(enc,b,q), h*64+hd] ----
    float inv0 = 1.f / l0r;
    float inv1 = 1.f / l1r;
    size_t base0 = ((size_t)(enc_q*B_ + b)*L_ + qg0)*D_ + h*64 + cq*2;
    size_t base1 = ((size_t)(enc_q*B_ + b)*L_ + qg1)*D_ + h*64 + cq*2;
    #pragma unroll
    for (int nt = 0; nt < 8; nt++) {
        float2 w0, w1;
        w0.x = o_acc[nt][0]*inv0; w0.y = o_acc[nt][1]*inv0;
        w1.x = o_acc[nt][2]*inv1; w1.y = o_acc[nt][3]*inv1;
        *(float2*)&g_ctx[base0 + nt*8] = w0;
        *(float2*)&g_ctx[base1 + nt*8] = w1;
    }
}

// ---------------------------------------------------------------------------
extern "C" void kernel_launch(void* const* d_in, const int* in_sizes, int n_in,
                              void* d_out, int out_size)
{
    const float* u_enc     = (const float*)d_in[0];
    const float* e_enc     = (const float*)d_in[1];
    const float* logit_bpp = (const float*)d_in[2];
    const void*  ue_mask   = d_in[3];
    const void*  eu_mask   = d_in[4];
    const float* wq_k = (const float*)d_in[5];
    const float* wq_b = (const float*)d_in[6];
    const float* wk_k = (const float*)d_in[7];
    const float* wk_b = (const float*)d_in[8];
    const float* wv_k = (const float*)d_in[9];
    const float* wv_b = (const float*)d_in[10];
    const float* wo_k = (const float*)d_in[11];
    const float* wo_b = (const float*)d_in[12];
    const float* bpp_w = (const float*)d_in[13];
    const float* bpp_b = (const float*)d_in[14];
    float* out = (float*)d_out;

    cudaFuncSetAttribute((const void*)attn_mma_kernel,
                         cudaFuncAttributeMaxDynamicSharedMemorySize, AT_SMEM);
    cudaFuncSetAttribute((const void*)gemm_mma_kernel,
                         cudaFuncAttributeMaxDynamicSharedMemorySize, GM_SMEM);

    // 0) mask dtype detection + expansion to uint8
    mask_detect_kernel<<<1, 256>>>((const unsigned int*)ue_mask);
    mask_expand_kernel<<<dim3(4096, 1, 2), 256>>>(ue_mask, eu_mask);
    // 1) fused QKV projections on tensor pipe (z: 0=q,1=k,2=v)
    gemm_mma_kernel<<<dim3(8, 64, 3), 256, GM_SMEM>>>(u_enc, e_enc,
                                                      wq_k, wk_k, wv_k,
                                                      wq_b, wk_b, wv_b,
                                                      nullptr, 0);
    // 2) bias prep
    bpp_prep_kernel<<<dim3(32, 32), dim3(32, 8)>>>(logit_bpp, bpp_w, bpp_b);
    // 3) fused attention on tensor pipe, both directions
    attn_mma_kernel<<<dim3(16, 32, 2), 128, AT_SMEM>>>();
    // 4) output projection on tensor pipe -> d_out
    gemm_mma_kernel<<<dim3(8, 64, 1), 256, GM_SMEM>>>(nullptr, nullptr,
                                                      wo_k, nullptr, nullptr,
                                                      wo_b, nullptr, nullptr,
                                                      out, 3);
}

// round 6
// speedup vs baseline: 2.2816x; 1.3240x over previous
#include <cuda_runtime.h>
#include <cuda_bf16.h>
#include <math.h>
#include <float.h>
#include <stdint.h>
#include <string.h>

#define B_  4
#define L_  1024
#define D_  512
#define H_  8
#define HD_ 64
#define PROJ_ELEMS (2*B_*H_*L_*HD_)   /* 4,194,304 */
#define MASK_ELEMS ((size_t)B_*L_*L_) /* 4,194,304 */
#define ENC_ELEMS  (8192*512)

// producer-split bf16 hi/lo storage
__device__ unsigned short g_ah[ENC_ELEMS], g_al[ENC_ELEMS];      // [u;e] inputs
__device__ unsigned short g_wth[4*512*512], g_wtl[4*512*512];    // W^T, n-major
__device__ unsigned short g_qh[PROJ_ELEMS], g_ql[PROJ_ELEMS];
__device__ unsigned short g_kh[PROJ_ELEMS], g_kl[PROJ_ELEMS];
__device__ unsigned short g_vh[PROJ_ELEMS], g_vl[PROJ_ELEMS];
__device__ unsigned short g_ch[PROJ_ELEMS], g_cl[PROJ_ELEMS];    // ctx hi/lo
__device__ float g_bpp[L_*L_];
__device__ float g_bppT[L_*L_];
__device__ float g_mb[2*B_*L_*L_];                               // bias+mask fused
__device__ int g_mtype;

// ===========================================================================
// helpers
// ===========================================================================
__device__ __forceinline__ uint32_t smem_u32(const void* p) {
    uint32_t a;
    asm("{ .reg .u64 t; cvta.to.shared.u64 t, %1; cvt.u32.u64 %0, t; }"
        : "=r"(a) : "l"(p));
    return a;
}
__device__ __forceinline__ void ldsm_x4(uint32_t& r0, uint32_t& r1,
                                        uint32_t& r2, uint32_t& r3,
                                        uint32_t addr) {
    asm volatile("ldmatrix.sync.aligned.m8n8.x4.shared.b16 {%0,%1,%2,%3}, [%4];"
                 : "=r"(r0), "=r"(r1), "=r"(r2), "=r"(r3) : "r"(addr));
}
__device__ __forceinline__ void ldsm_x4_t(uint32_t& r0, uint32_t& r1,
                                          uint32_t& r2, uint32_t& r3,
                                          uint32_t addr) {
    asm volatile("ldmatrix.sync.aligned.m8n8.x4.trans.shared.b16 {%0,%1,%2,%3}, [%4];"
                 : "=r"(r0), "=r"(r1), "=r"(r2), "=r"(r3) : "r"(addr));
}
__device__ __forceinline__ void mma_bf16(float* c, const uint32_t* a,
                                         const uint32_t* b) {
    asm volatile("mma.sync.aligned.m16n8k16.row.col.f32.bf16.bf16.f32 "
                 "{%0,%1,%2,%3}, {%4,%5,%6,%7}, {%8,%9}, {%0,%1,%2,%3};"
                 : "+f"(c[0]), "+f"(c[1]), "+f"(c[2]), "+f"(c[3])
                 : "r"(a[0]), "r"(a[1]), "r"(a[2]), "r"(a[3]),
                   "r"(b[0]), "r"(b[1]));
}
__device__ __forceinline__ unsigned short f2bf_bits(float x) {
    __nv_bfloat16 h = __float2bfloat16(x);
    unsigned short u; memcpy(&u, &h, 2); return u;
}
__device__ __forceinline__ float bfbits2f(unsigned short u) {
    __nv_bfloat16 h; memcpy(&h, &u, 2); return __bfloat162float(h);
}
__device__ __forceinline__ void split2(float x, float y, uint32_t& hi, uint32_t& lo) {
    unsigned short hx = f2bf_bits(x), hy = f2bf_bits(y);
    unsigned short lx = f2bf_bits(x - bfbits2f(hx));
    unsigned short ly = f2bf_bits(y - bfbits2f(hy));
    hi = (uint32_t)hx | ((uint32_t)hy << 16);
    lo = (uint32_t)lx | ((uint32_t)ly << 16);
}

// ===========================================================================
// Mask dtype detection (unchanged)
// ===========================================================================
__global__ void mask_detect_kernel(const unsigned int* __restrict__ m)
{
    __shared__ int viol[3];
    if (threadIdx.x < 3) viol[threadIdx.x] = 0;
    __syncthreads();
    int v0 = 0, v1 = 0, v2 = 0;
    for (int i = threadIdx.x; i < 16384; i += 256) {
        unsigned w = m[i];
        if (w > 1u) v0 = 1;
        if (w != 0u && w != 0x3F800000u) v1 = 1;
        if (w != 0u && w != 0x3F800000u && w != 0x00003F80u && w != 0x3F803F80u) v2 = 1;
    }
    if (v0) atomicOr(&viol[0], 1);
    if (v1) atomicOr(&viol[1], 1);
    if (v2) atomicOr(&viol[2], 1);
    __syncthreads();
    if (threadIdx.x == 0) {
        int t;
        if      (!viol[0]) t = 1;
        else if (!viol[1]) t = 2;
        else if (!viol[2]) t = 3;
        else               t = 0;
        g_mtype = t;
    }
}

// ===========================================================================
// bpp prep: g_bpp = w*lb + b ; g_bppT = transpose
// ===========================================================================
__global__ __launch_bounds__(256) void bpp_prep_kernel(
    const float* __restrict__ lb,
    const float* __restrict__ wp,
    const float* __restrict__ bp)
{
    __shared__ float t[32][33];
    int tx = threadIdx.x, ty = threadIdx.y;
    float w = wp[0], bb = bp[0];
    int x  = blockIdx.x*32 + tx;
    int y0 = blockIdx.y*32;
    #pragma unroll
    for (int i = ty; i < 32; i += 8) {
        float v = fmaf(w, lb[(size_t)(y0+i)*L_ + x], bb);
        g_bpp[(size_t)(y0+i)*L_ + x] = v;
        t[i][tx] = v;
    }
    __syncthreads();
    int xo = y0 + tx;
    #pragma unroll
    for (int i = ty; i < 32; i += 8) {
        g_bppT[(size_t)(blockIdx.x*32+i)*L_ + xo] = t[tx][i];
    }
}

// ===========================================================================
// maskbias: g_mb[dir][b][q][k] = mask ? bias : -1e38 (additive fold)
// grid (4096,1,2) x 256
// ===========================================================================
__global__ __launch_bounds__(256) void maskbias_kernel(
    const void* __restrict__ ue, const void* __restrict__ eu)
{
    int t = g_mtype;
    int dir = blockIdx.z;
    const void* src = dir ? eu : ue;
    const float* bp = dir ? g_bppT : g_bpp;
    float* dst = g_mb + (size_t)dir * MASK_ELEMS;
    size_t stride = (size_t)gridDim.x * blockDim.x;
    for (size_t i = (size_t)blockIdx.x*blockDim.x + threadIdx.x;
         i < MASK_ELEMS; i += stride) {
        bool mv;
        if      (t == 1) mv = ((const int*)src)[i] != 0;
        else if (t == 2) mv = ((const float*)src)[i] != 0.f;
        else if (t == 3) mv = ((const unsigned short*)src)[i] != 0;
        else             mv = ((const unsigned char*)src)[i] != 0;
        float bias = bp[i & (L_*L_ - 1)];
        dst[i] = mv ? bias : -1.0e38f;
    }
}

// ===========================================================================
// enc split: [u_enc ; e_enc] fp32 -> g_ah/g_al bf16 hi/lo.  grid (1024,1,2)x256
// ===========================================================================
__global__ __launch_bounds__(256) void enc_split_kernel(
    const float* __restrict__ u, const float* __restrict__ e)
{
    const float* src = blockIdx.z ? e : u;
    size_t base4 = (size_t)blockIdx.z * (4096*512/4);
    size_t stride = (size_t)gridDim.x * blockDim.x;
    for (size_t i4 = (size_t)blockIdx.x*blockDim.x + threadIdx.x;
         i4 < 4096*512/4; i4 += stride) {
        float4 v = ((const float4*)src)[i4];
        uint32_t h01, l01, h23, l23;
        split2(v.x, v.y, h01, l01);
        split2(v.z, v.w, h23, l23);
        ((uint2*)g_ah)[base4 + i4] = make_uint2(h01, h23);
        ((uint2*)g_al)[base4 + i4] = make_uint2(l01, l23);
    }
}

// ===========================================================================
// weight transpose+split: W[k][n] fp32 -> Wt[n][k] bf16 hi/lo.
// grid (16,16,4) block (32,8).  z: 0=wq 1=wk 2=wv 3=wo
// ===========================================================================
__global__ __launch_bounds__(256) void wt_split_kernel(
    const float* __restrict__ wq, const float* __restrict__ wk,
    const float* __restrict__ wv, const float* __restrict__ wo)
{
    const float* src = (blockIdx.z == 0) ? wq : (blockIdx.z == 1) ? wk
                     : (blockIdx.z == 2) ? wv : wo;
    __shared__ float t[32][33];
    int tx = threadIdx.x, ty = threadIdx.y;
    int x  = blockIdx.x*32 + tx;
    int y0 = blockIdx.y*32;
    #pragma unroll
    for (int i = ty; i < 32; i += 8)
        t[i][tx] = src[(size_t)(y0+i)*512 + x];
    __syncthreads();
    size_t base = (size_t)blockIdx.z * 512*512;
    int ko = y0 + tx;
    #pragma unroll
    for (int i = ty; i < 32; i += 8) {
        float v = t[tx][i];
        unsigned short h = f2bf_bits(v);
        unsigned short l = f2bf_bits(v - bfbits2f(h));
        size_t idx = base + (size_t)(blockIdx.x*32+i)*512 + ko;
        g_wth[idx] = h;
        g_wtl[idx] = l;
    }
}

// ===========================================================================
// GEMM (copy-only fills): [8192 x 512] * [512 x 512] + bias.
//   Block 128(M) x 64(N), K chunks of 64, 256 threads (8 warps 4x2).
//   mode 0/1/2: A=g_ah/g_al, Wt slot mode, epilogue -> bf16 hi/lo qkv arrays.
//   mode 3: A=g_ch/g_cl (ctx), Wt slot 3, epilogue -> fp32 outp.
// ===========================================================================
#define AS_ 72
#define GM_A_HI 0
#define GM_A_LO 18432
#define GM_B_HI 36864
#define GM_B_LO 46080
#define GM_SMEM 55296

__global__ __launch_bounds__(256) void gemm_mma_kernel(
    const float* __restrict__ bq, const float* __restrict__ bk,
    const float* __restrict__ bv, const float* __restrict__ bo,
    float* __restrict__ outp, int modebase)
{
    extern __shared__ __align__(16) unsigned char smem[];
    uint32_t sbase = smem_u32(smem);

    int tid = threadIdx.x;
    int wid = tid >> 5, lane = tid & 31;
    int wm = wid & 3, wn = wid >> 2;

    int mode = modebase + blockIdx.z;
    const float* bias;
    unsigned short *dsth, *dstl;
    if      (mode == 0) { bias = bq; dsth = g_qh; dstl = g_ql; }
    else if (mode == 1) { bias = bk; dsth = g_kh; dstl = g_kl; }
    else if (mode == 2) { bias = bv; dsth = g_vh; dstl = g_vl; }
    else                { bias = bo; dsth = 0;    dstl = 0;    }

    const unsigned short* Ah = (mode < 3) ? g_ah : g_ch;
    const unsigned short* Al = (mode < 3) ? g_al : g_cl;
    int widx = (mode < 3) ? mode : 3;
    const unsigned short* Bh = g_wth + (size_t)widx*512*512;
    const unsigned short* Bl = g_wtl + (size_t)widx*512*512;

    int n0   = blockIdx.x * 64;
    int row0 = blockIdx.y * 128;

    float acc[2][4][4];
    #pragma unroll
    for (int mi = 0; mi < 2; mi++)
        #pragma unroll
        for (int ni = 0; ni < 4; ni++)
            #pragma unroll
            for (int c = 0; c < 4; c++) acc[mi][ni][c] = 0.f;

    for (int kb = 0; kb < 8; kb++) {
        int kbase = kb * 64;
        __syncthreads();

        // A fill: 128 rows x 8 uint4 per array (hi: i=0..3, lo: i=4..7)
        #pragma unroll
        for (int i = 0; i < 8; i++) {
            int idx = i*256 + tid;
            int a = idx >> 10;                    // 0 hi, 1 lo
            int rem = idx & 1023;
            int row = rem >> 3, q8 = rem & 7;
            const unsigned short* srcp = a ? Al : Ah;
            uint4 v = *(const uint4*)&srcp[(size_t)(row0+row)*512 + kbase + q8*8];
            *(uint4*)(smem + (a ? GM_A_LO : GM_A_HI) + row*144 + q8*16) = v;
        }
        // B fill: 64 n-rows x 8 uint4 per array (hi: i=0..1, lo: i=2..3)
        #pragma unroll
        for (int i = 0; i < 4; i++) {
            int idx = i*256 + tid;
            int a = idx >> 9;
            int rem = idx & 511;
            int row = rem >> 3, q8 = rem & 7;
            const unsigned short* srcp = a ? Bl : Bh;
            uint4 v = *(const uint4*)&srcp[(size_t)(n0+row)*512 + kbase + q8*8];
            *(uint4*)(smem + (a ? GM_B_LO : GM_B_HI) + row*144 + q8*16) = v;
        }
        __syncthreads();

        #pragma unroll
        for (int ks = 0; ks < 4; ks++) {
            uint32_t a_hi[2][4], a_lo[2][4], b_hi[8], b_lo[8];
            #pragma unroll
            for (int mi = 0; mi < 2; mi++) {
                int row = wm*32 + mi*16 + (lane & 15);
                int kcol = ks*16 + ((lane >> 4) << 3);
                uint32_t off = (uint32_t)(row*(AS_*2) + kcol*2);
                ldsm_x4(a_hi[mi][0], a_hi[mi][1], a_hi[mi][2], a_hi[mi][3],
                        sbase + GM_A_HI + off);
                ldsm_x4(a_lo[mi][0], a_lo[mi][1], a_lo[mi][2], a_lo[mi][3],
                        sbase + GM_A_LO + off);
            }
            #pragma unroll
            for (int g = 0; g < 2; g++) {
                int rr = lane & 7;
                int hk = (lane >> 3) & 1;
                int hn = (lane >> 4) & 1;
                int nrow = wn*32 + g*16 + hn*8 + rr;
                int kcol = ks*16 + hk*8;
                uint32_t off = (uint32_t)(nrow*(AS_*2) + kcol*2);
                ldsm_x4(b_hi[g*4+0], b_hi[g*4+1], b_hi[g*4+2], b_hi[g*4+3],
                        sbase + GM_B_HI + off);
                ldsm_x4(b_lo[g*4+0], b_lo[g*4+1], b_lo[g*4+2], b_lo[g*4+3],
                        sbase + GM_B_LO + off);
            }
            #pragma unroll
            for (int mi = 0; mi < 2; mi++) {
                #pragma unroll
                for (int ni = 0; ni < 4; ni++) {
                    mma_bf16(acc[mi][ni], a_hi[mi], &b_hi[ni*2]);
                    mma_bf16(acc[mi][ni], a_lo[mi], &b_hi[ni*2]);
                    mma_bf16(acc[mi][ni], a_hi[mi], &b_lo[ni*2]);
                }
            }
        }
    }

    float scale = (mode == 0) ? 0.125f : 1.f;
    #pragma unroll
    for (int mi = 0; mi < 2; mi++) {
        #pragma unroll
        for (int ni = 0; ni < 4; ni++) {
            int nl = wn*32 + ni*8 + (lane & 3)*2;
            float b0 = bias[n0 + nl], b1 = bias[n0 + nl + 1];
            #pragma unroll
            for (int half = 0; half < 2; half++) {
                int m = row0 + wm*32 + mi*16 + (lane >> 2) + half*8;
                float ox = (acc[mi][ni][half*2+0] + b0) * scale;
                float oy = (acc[mi][ni][half*2+1] + b1) * scale;
                if (mode < 3) {
                    int enc = m >> 12, b = (m >> 10) & 3, l = m & 1023;
                    int h = n0 >> 6;
                    size_t idx = ((((size_t)(enc*B_ + b))*H_ + h)*L_ + l)*HD_ + nl;
                    uint32_t hi, lo;
                    split2(ox, oy, hi, lo);
                    *(uint32_t*)&dsth[idx] = hi;
                    *(uint32_t*)&dstl[idx] = lo;
                } else {
                    float2 o; o.x = ox; o.y = oy;
                    *(float2*)&outp[(size_t)m*D_ + n0 + nl] = o;
                }
            }
        }
    }
}

// ===========================================================================
// Flash attention on mma.sync — copy-only fills (operands pre-split),
// additive mask+bias, ctx written as bf16 hi/lo.
//   grid (16 qtiles, 32 b*h, 2 dirs), 128 threads (4 warps).
// ===========================================================================
#define AT_QH 0
#define AT_QL 9216
#define AT_KH 18432
#define AT_KL 27648
#define AT_VH 36864
#define AT_VL 46080
#define AT_SMEM 55296

__global__ __launch_bounds__(128) void attn_mma_kernel()
{
    extern __shared__ __align__(16) unsigned char smem[];
    uint32_t sbase = smem_u32(smem);

    int tid = threadIdx.x;
    int wid = tid >> 5, lane = tid & 31;
    int r = lane >> 2, cq = lane & 3;

    int qt = blockIdx.x, bh = blockIdx.y, dir = blockIdx.z;
    int b = bh >> 3, h = bh & 7;
    int enc_q = dir, enc_kv = 1 - dir;

    size_t qoff  = ((size_t)((enc_q *B_ + b)*H_ + h))*L_*HD_;
    size_t kvoff = ((size_t)((enc_kv*B_ + b)*H_ + h))*L_*HD_;
    const unsigned short* Qh = g_qh + qoff;
    const unsigned short* Ql = g_ql + qoff;
    const unsigned short* Kh = g_kh + kvoff;
    const unsigned short* Kl = g_kl + kvoff;
    const unsigned short* Vh = g_vh + kvoff;
    const unsigned short* Vl = g_vl + kvoff;
    const float* mb = g_mb + ((size_t)dir*B_ + b)*L_*L_;
    int q0 = qt * 64;

    // ---- Q tile copy (64 rows x 8 uint4, hi+lo) ----
    #pragma unroll
    for (int i = 0; i < 8; i++) {
        int idx = i*128 + tid;
        int a = idx >> 9;
        int rem = idx & 511;
        int row = rem >> 3, q8 = rem & 7;
        const unsigned short* srcp = a ? Ql : Qh;
        uint4 v = *(const uint4*)&srcp[(size_t)(q0+row)*HD_ + q8*8];
        *(uint4*)(smem + (a ? AT_QL : AT_QH) + row*144 + q8*16) = v;
    }
    __syncthreads();

    // ---- Q A-fragments resident in regs ----
    uint32_t aq_h[4][4], aq_l[4][4];
    #pragma unroll
    for (int ks = 0; ks < 4; ks++) {
        int row = wid*16 + (lane & 15);
        int kcol = ks*16 + ((lane >> 4) << 3);
        uint32_t off = (uint32_t)(row*(AS_*2) + kcol*2);
        ldsm_x4(aq_h[ks][0], aq_h[ks][1], aq_h[ks][2], aq_h[ks][3], sbase + AT_QH + off);
        ldsm_x4(aq_l[ks][0], aq_l[ks][1], aq_l[ks][2], aq_l[ks][3], sbase + AT_QL + off);
    }

    float o_acc[8][4];
    #pragma unroll
    for (int nt = 0; nt < 8; nt++)
        #pragma unroll
        for (int c = 0; c < 4; c++) o_acc[nt][c] = 0.f;
    float m0r = -3.0e38f, m1r = -3.0e38f, l0r = 0.f, l1r = 0.f;

    int qg0 = q0 + wid*16 + r;
    int qg1 = qg0 + 8;
    const float* mb0 = mb + (size_t)qg0*L_ + cq*2;
    const float* mb1 = mb + (size_t)qg1*L_ + cq*2;

    for (int t = 0; t < 16; t++) {
        int k0 = t * 64;
        __syncthreads();

        // ---- K/V tile copy: 4 arrays x 512 uint4 / 128 thr = 16 iters ----
        #pragma unroll
        for (int i = 0; i < 16; i++) {
            int idx = i*128 + tid;
            int a = idx >> 9;                  // 0=KH 1=KL 2=VH 3=VL
            int rem = idx & 511;
            int row = rem >> 3, q8 = rem & 7;
            const unsigned short* srcp = (a == 0) ? Kh : (a == 1) ? Kl
                                       : (a == 2) ? Vh : Vl;
            int dsto = (a == 0) ? AT_KH : (a == 1) ? AT_KL
                     : (a == 2) ? AT_VH : AT_VL;
            uint4 v = *(const uint4*)&srcp[(size_t)(k0+row)*HD_ + q8*8];
            *(uint4*)(smem + dsto + row*144 + q8*16) = v;
        }
        __syncthreads();

        // ---- S = Q K^T ----
        float s_acc[8][4];
        #pragma unroll
        for (int nt = 0; nt < 8; nt++)
            #pragma unroll
            for (int c = 0; c < 4; c++) s_acc[nt][c] = 0.f;

        #pragma unroll
        for (int ks = 0; ks < 4; ks++) {
            #pragma unroll
            for (int g = 0; g < 4; g++) {
                uint32_t bk_h[4], bk_l[4];
                int rr = lane & 7;
                int hk = (lane >> 3) & 1;
                int hn = (lane >> 4) & 1;
                int nrow = g*16 + hn*8 + rr;
                int kcol = ks*16 + hk*8;
                uint32_t off = (uint32_t)(nrow*(AS_*2) + kcol*2);
                ldsm_x4(bk_h[0], bk_h[1], bk_h[2], bk_h[3], sbase + AT_KH + off);
                ldsm_x4(bk_l[0], bk_l[1], bk_l[2], bk_l[3], sbase + AT_KL + off);
                #pragma unroll
                for (int sub = 0; sub < 2; sub++) {
                    int nt = g*2 + sub;
                    mma_bf16(s_acc[nt], aq_h[ks], &bk_h[sub*2]);
                    mma_bf16(s_acc[nt], aq_l[ks], &bk_h[sub*2]);
                    mma_bf16(s_acc[nt], aq_h[ks], &bk_l[sub*2]);
                }
            }
        }

        // ---- additive mask+bias ----
        #pragma unroll
        for (int nt = 0; nt < 8; nt++) {
            int cc = k0 + nt*8;
            float2 b0v = *(const float2*)&mb0[cc];
            float2 b1v = *(const float2*)&mb1[cc];
            s_acc[nt][0] += b0v.x;
            s_acc[nt][1] += b0v.y;
            s_acc[nt][2] += b1v.x;
            s_acc[nt][3] += b1v.y;
        }

        // ---- online softmax ----
        float mx0 = -3.0e38f, mx1 = -3.0e38f;
        #pragma unroll
        for (int nt = 0; nt < 8; nt++) {
            mx0 = fmaxf(mx0, fmaxf(s_acc[nt][0], s_acc[nt][1]));
            mx1 = fmaxf(mx1, fmaxf(s_acc[nt][2], s_acc[nt][3]));
        }
        mx0 = fmaxf(mx0, __shfl_xor_sync(0xffffffffu, mx0, 1));
        mx0 = fmaxf(mx0, __shfl_xor_sync(0xffffffffu, mx0, 2));
        mx1 = fmaxf(mx1, __shfl_xor_sync(0xffffffffu, mx1, 1));
        mx1 = fmaxf(mx1, __shfl_xor_sync(0xffffffffu, mx1, 2));

        float mn0 = fmaxf(m0r, mx0);
        float mn1 = fmaxf(m1r, mx1);
        float c0 = __expf(m0r - mn0);
        float c1 = __expf(m1r - mn1);
        m0r = mn0; m1r = mn1;

        float rs0 = 0.f, rs1 = 0.f;
        #pragma unroll
        for (int nt = 0; nt < 8; nt++) {
            s_acc[nt][0] = __expf(s_acc[nt][0] - m0r); rs0 += s_acc[nt][0];
            s_acc[nt][1] = __expf(s_acc[nt][1] - m0r); rs0 += s_acc[nt][1];
            s_acc[nt][2] = __expf(s_acc[nt][2] - m1r); rs1 += s_acc[nt][2];
            s_acc[nt][3] = __expf(s_acc[nt][3] - m1r); rs1 += s_acc[nt][3];
        }
        rs0 += __shfl_xor_sync(0xffffffffu, rs0, 1);
        rs0 += __shfl_xor_sync(0xffffffffu, rs0, 2);
        rs1 += __shfl_xor_sync(0xffffffffu, rs1, 1);
        rs1 += __shfl_xor_sync(0xffffffffu, rs1, 2);
        l0r = l0r*c0 + rs0;
        l1r = l1r*c1 + rs1;

        #pragma unroll
        for (int nt = 0; nt < 8; nt++) {
            o_acc[nt][0] *= c0; o_acc[nt][1] *= c0;
            o_acc[nt][2] *= c1; o_acc[nt][3] *= c1;
        }

        // ---- O += P V (P split in regs) ----
        #pragma unroll
        for (int ks = 0; ks < 4; ks++) {
            int t0 = 2*ks, t1 = 2*ks + 1;
            uint32_t ap_h[4], ap_l[4];
            split2(s_acc[t0][0], s_acc[t0][1], ap_h[0], ap_l[0]);
            split2(s_acc[t0][2], s_acc[t0][3], ap_h[1], ap_l[1]);
            split2(s_acc[t1][0], s_acc[t1][1], ap_h[2], ap_l[2]);
            split2(s_acc[t1][2], s_acc[t1][3], ap_h[3], ap_l[3]);
            #pragma unroll
            for (int g = 0; g < 4; g++) {
                uint32_t bv_h[4], bv_l[4];
                int kk  = ks*16 + ((lane >> 3) & 1)*8 + (lane & 7);
                int hdo = g*16 + ((lane >> 4) & 1)*8;
                uint32_t off = (uint32_t)(kk*(AS_*2) + hdo*2);
                ldsm_x4_t(bv_h[0], bv_h[1], bv_h[2], bv_h[3], sbase + AT_VH + off);
                ldsm_x4_t(bv_l[0], bv_l[1], bv_l[2], bv_l[3], sbase + AT_VL + off);
                #pragma unroll
                for (int sub = 0; sub < 2; sub++) {
                    int nt = g*2 + sub;
                    mma_bf16(o_acc[nt], ap_h, &bv_h[sub*2]);
                    mma_bf16(o_acc[nt], ap_l, &bv_h[sub*2]);
                    mma_bf16(o_acc[nt], ap_h, &bv_l[sub*2]);
                }
            }
        }
    }

    // ---- finalize: ctx = O/l as bf16 hi/lo ----
    float inv0 = 1.f / l0r;
    float inv1 = 1.f / l1r;
    size_t base0 = ((size_t)(enc_q*B_ + b)*L_ + qg0)*D_ + h*64 + cq*2;
    size_t base1 = ((size_t)(enc_q*B_ + b)*L_ + qg1)*D_ + h*64 + cq*2;
    #pragma unroll
    for (int nt = 0; nt < 8; nt++) {
        uint32_t hi0, lo0, hi1, lo1;
        split2(o_acc[nt][0]*inv0, o_acc[nt][1]*inv0, hi0, lo0);
        split2(o_acc[nt][2]*inv1, o_acc[nt][3]*inv1, hi1, lo1);
        *(uint32_t*)&g_ch[base0 + nt*8] = hi0;
        *(uint32_t*)&g_cl[base0 + nt*8] = lo0;
        *(uint32_t*)&g_ch[base1 + nt*8] = hi1;
        *(uint32_t*)&g_cl[base1 + nt*8] = lo1;
    }
}

// ---------------------------------------------------------------------------
extern "C" void kernel_launch(void* const* d_in, const int* in_sizes, int n_in,
                              void* d_out, int out_size)
{
    const float* u_enc     = (const float*)d_in[0];
    const float* e_enc     = (const float*)d_in[1];
    const float* logit_bpp = (const float*)d_in[2];
    const void*  ue_mask   = d_in[3];
    const void*  eu_mask   = d_in[4];
    const float* wq_k = (const float*)d_in[5];
    const float* wq_b = (const float*)d_in[6];
    const float* wk_k = (const float*)d_in[7];
    const float* wk_b = (const float*)d_in[8];
    const float* wv_k = (const float*)d_in[9];
    const float* wv_b = (const float*)d_in[10];
    const float* wo_k = (const float*)d_in[11];
    const float* wo_b = (const float*)d_in[12];
    const float* bpp_w = (const float*)d_in[13];
    const float* bpp_b = (const float*)d_in[14];
    float* out = (float*)d_out;

    cudaFuncSetAttribute((const void*)attn_mma_kernel,
                         cudaFuncAttributeMaxDynamicSharedMemorySize, AT_SMEM);
    cudaFuncSetAttribute((const void*)gemm_mma_kernel,
                         cudaFuncAttributeMaxDynamicSharedMemorySize, GM_SMEM);

    // 0) mask dtype detection
    mask_detect_kernel<<<1, 256>>>((const unsigned int*)ue_mask);
    // 1) bias prep (bpp, bpp^T) then fused mask+bias
    bpp_prep_kernel<<<dim3(32, 32), dim3(32, 8)>>>(logit_bpp, bpp_w, bpp_b);
    maskbias_kernel<<<dim3(4096, 1, 2), 256>>>(ue_mask, eu_mask);
    // 2) one-time operand splits
    enc_split_kernel<<<dim3(1024, 1, 2), 256>>>(u_enc, e_enc);
    wt_split_kernel<<<dim3(16, 16, 4), dim3(32, 8)>>>(wq_k, wk_k, wv_k, wo_k);
    // 3) fused QKV projections (z: 0=q,1=k,2=v) -> bf16 hi/lo
    gemm_mma_kernel<<<dim3(8, 64, 3), 256, GM_SMEM>>>(wq_b, wk_b, wv_b, wo_b,
                                                      nullptr, 0);
    // 4) fused attention, both directions -> ctx bf16 hi/lo
    attn_mma_kernel<<<dim3(16, 32, 2), 128, AT_SMEM>>>();
    // 5) output projection -> d_out
    gemm_mma_kernel<<<dim3(8, 64, 1), 256, GM_SMEM>>>(wq_b, wk_b, wv_b, wo_b,
                                                      out, 3);
}

// round 7
// speedup vs baseline: 2.4437x; 1.0710x over previous
#include <cuda_runtime.h>
#include <cuda_bf16.h>
#include <math.h>
#include <float.h>
#include <stdint.h>
#include <string.h>

#define B_  4
#define L_  1024
#define D_  512
#define H_  8
#define HD_ 64
#define PROJ_ELEMS (2*B_*H_*L_*HD_)   /* 4,194,304 */
#define MASK_ELEMS ((size_t)B_*L_*L_) /* 4,194,304 */
#define ENC_ELEMS  (8192*512)

// producer-split bf16 hi/lo storage
__device__ unsigned short g_ah[ENC_ELEMS], g_al[ENC_ELEMS];      // [u;e] inputs
__device__ unsigned short g_wth[4*512*512], g_wtl[4*512*512];    // W^T, n-major
__device__ unsigned short g_qh[PROJ_ELEMS], g_ql[PROJ_ELEMS];
__device__ unsigned short g_kh[PROJ_ELEMS], g_kl[PROJ_ELEMS];
__device__ unsigned short g_vh[PROJ_ELEMS], g_vl[PROJ_ELEMS];
__device__ unsigned short g_ch[PROJ_ELEMS], g_cl[PROJ_ELEMS];    // ctx hi/lo
__device__ float g_bpp[L_*L_];
__device__ float g_bppT[L_*L_];
__device__ float g_mb[2*B_*L_*L_];                               // bias+mask fused
__device__ int g_mtype;

// ===========================================================================
// helpers
// ===========================================================================
__device__ __forceinline__ uint32_t smem_u32(const void* p) {
    uint32_t a;
    asm("{ .reg .u64 t; cvta.to.shared.u64 t, %1; cvt.u32.u64 %0, t; }"
        : "=r"(a) : "l"(p));
    return a;
}
#define CP_ASYNC16(saddr, gptr) \
    asm volatile("cp.async.ca.shared.global [%0], [%1], 16;" \
                 :: "r"(saddr), "l"(gptr))
#define CP_COMMIT() asm volatile("cp.async.commit_group;" ::: "memory")
#define CP_WAIT0()  asm volatile("cp.async.wait_group 0;" ::: "memory")

__device__ __forceinline__ void ldsm_x4(uint32_t& r0, uint32_t& r1,
                                        uint32_t& r2, uint32_t& r3,
                                        uint32_t addr) {
    asm volatile("ldmatrix.sync.aligned.m8n8.x4.shared.b16 {%0,%1,%2,%3}, [%4];"
                 : "=r"(r0), "=r"(r1), "=r"(r2), "=r"(r3) : "r"(addr));
}
__device__ __forceinline__ void ldsm_x4_t(uint32_t& r0, uint32_t& r1,
                                          uint32_t& r2, uint32_t& r3,
                                          uint32_t addr) {
    asm volatile("ldmatrix.sync.aligned.m8n8.x4.trans.shared.b16 {%0,%1,%2,%3}, [%4];"
                 : "=r"(r0), "=r"(r1), "=r"(r2), "=r"(r3) : "r"(addr));
}
__device__ __forceinline__ void mma_bf16(float* c, const uint32_t* a,
                                         const uint32_t* b) {
    asm volatile("mma.sync.aligned.m16n8k16.row.col.f32.bf16.bf16.f32 "
                 "{%0,%1,%2,%3}, {%4,%5,%6,%7}, {%8,%9}, {%0,%1,%2,%3};"
                 : "+f"(c[0]), "+f"(c[1]), "+f"(c[2]), "+f"(c[3])
                 : "r"(a[0]), "r"(a[1]), "r"(a[2]), "r"(a[3]),
                   "r"(b[0]), "r"(b[1]));
}
__device__ __forceinline__ unsigned short f2bf_bits(float x) {
    __nv_bfloat16 h = __float2bfloat16(x);
    unsigned short u; memcpy(&u, &h, 2); return u;
}
__device__ __forceinline__ float bfbits2f(unsigned short u) {
    __nv_bfloat16 h; memcpy(&h, &u, 2); return __bfloat162float(h);
}
__device__ __forceinline__ void split2(float x, float y, uint32_t& hi, uint32_t& lo) {
    unsigned short hx = f2bf_bits(x), hy = f2bf_bits(y);
    unsigned short lx = f2bf_bits(x - bfbits2f(hx));
    unsigned short ly = f2bf_bits(y - bfbits2f(hy));
    hi = (uint32_t)hx | ((uint32_t)hy << 16);
    lo = (uint32_t)lx | ((uint32_t)ly << 16);
}

// ===========================================================================
// Mask dtype detection
// ===========================================================================
__global__ void mask_detect_kernel(const unsigned int* __restrict__ m)
{
    __shared__ int viol[3];
    if (threadIdx.x < 3) viol[threadIdx.x] = 0;
    __syncthreads();
    int v0 = 0, v1 = 0, v2 = 0;
    for (int i = threadIdx.x; i < 16384; i += 256) {
        unsigned w = m[i];
        if (w > 1u) v0 = 1;
        if (w != 0u && w != 0x3F800000u) v1 = 1;
        if (w != 0u && w != 0x3F800000u && w != 0x00003F80u && w != 0x3F803F80u) v2 = 1;
    }
    if (v0) atomicOr(&viol[0], 1);
    if (v1) atomicOr(&viol[1], 1);
    if (v2) atomicOr(&viol[2], 1);
    __syncthreads();
    if (threadIdx.x == 0) {
        int t;
        if      (!viol[0]) t = 1;
        else if (!viol[1]) t = 2;
        else if (!viol[2]) t = 3;
        else               t = 0;
        g_mtype = t;
    }
}

// ===========================================================================
// bpp prep
// ===========================================================================
__global__ __launch_bounds__(256) void bpp_prep_kernel(
    const float* __restrict__ lb,
    const float* __restrict__ wp,
    const float* __restrict__ bp)
{
    __shared__ float t[32][33];
    int tx = threadIdx.x, ty = threadIdx.y;
    float w = wp[0], bb = bp[0];
    int x  = blockIdx.x*32 + tx;
    int y0 = blockIdx.y*32;
    #pragma unroll
    for (int i = ty; i < 32; i += 8) {
        float v = fmaf(w, lb[(size_t)(y0+i)*L_ + x], bb);
        g_bpp[(size_t)(y0+i)*L_ + x] = v;
        t[i][tx] = v;
    }
    __syncthreads();
    int xo = y0 + tx;
    #pragma unroll
    for (int i = ty; i < 32; i += 8) {
        g_bppT[(size_t)(blockIdx.x*32+i)*L_ + xo] = t[tx][i];
    }
}

// ===========================================================================
// maskbias
// ===========================================================================
__global__ __launch_bounds__(256) void maskbias_kernel(
    const void* __restrict__ ue, const void* __restrict__ eu)
{
    int t = g_mtype;
    int dir = blockIdx.z;
    const void* src = dir ? eu : ue;
    const float* bp = dir ? g_bppT : g_bpp;
    float* dst = g_mb + (size_t)dir * MASK_ELEMS;
    size_t stride = (size_t)gridDim.x * blockDim.x;
    for (size_t i = (size_t)blockIdx.x*blockDim.x + threadIdx.x;
         i < MASK_ELEMS; i += stride) {
        bool mv;
        if      (t == 1) mv = ((const int*)src)[i] != 0;
        else if (t == 2) mv = ((const float*)src)[i] != 0.f;
        else if (t == 3) mv = ((const unsigned short*)src)[i] != 0;
        else             mv = ((const unsigned char*)src)[i] != 0;
        float bias = bp[i & (L_*L_ - 1)];
        dst[i] = mv ? bias : -1.0e38f;
    }
}

// ===========================================================================
// enc split
// ===========================================================================
__global__ __launch_bounds__(256) void enc_split_kernel(
    const float* __restrict__ u, const float* __restrict__ e)
{
    const float* src = blockIdx.z ? e : u;
    size_t base4 = (size_t)blockIdx.z * (4096*512/4);
    size_t stride = (size_t)gridDim.x * blockDim.x;
    for (size_t i4 = (size_t)blockIdx.x*blockDim.x + threadIdx.x;
         i4 < 4096*512/4; i4 += stride) {
        float4 v = ((const float4*)src)[i4];
        uint32_t h01, l01, h23, l23;
        split2(v.x, v.y, h01, l01);
        split2(v.z, v.w, h23, l23);
        ((uint2*)g_ah)[base4 + i4] = make_uint2(h01, h23);
        ((uint2*)g_al)[base4 + i4] = make_uint2(l01, l23);
    }
}

// ===========================================================================
// weight transpose+split
// ===========================================================================
__global__ __launch_bounds__(256) void wt_split_kernel(
    const float* __restrict__ wq, const float* __restrict__ wk,
    const float* __restrict__ wv, const float* __restrict__ wo)
{
    const float* src = (blockIdx.z == 0) ? wq : (blockIdx.z == 1) ? wk
                     : (blockIdx.z == 2) ? wv : wo;
    __shared__ float t[32][33];
    int tx = threadIdx.x, ty = threadIdx.y;
    int x  = blockIdx.x*32 + tx;
    int y0 = blockIdx.y*32;
    #pragma unroll
    for (int i = ty; i < 32; i += 8)
        t[i][tx] = src[(size_t)(y0+i)*512 + x];
    __syncthreads();
    size_t base = (size_t)blockIdx.z * 512*512;
    int ko = y0 + tx;
    #pragma unroll
    for (int i = ty; i < 32; i += 8) {
        float v = t[tx][i];
        unsigned short h = f2bf_bits(v);
        unsigned short l = f2bf_bits(v - bfbits2f(h));
        size_t idx = base + (size_t)(blockIdx.x*32+i)*512 + ko;
        g_wth[idx] = h;
        g_wtl[idx] = l;
    }
}

// ===========================================================================
// GEMM, cp.async double-buffered.
//   Block 128(M) x 64(N), K chunks of 64, 256 threads (8 warps 4x2).
// Stage layout (within buffer): AH 0, AL 18432, BH 36864, BL 46080; 55296/stage.
// ===========================================================================
#define AS_ 72
#define GM_BUF  55296
#define GM_AH   0
#define GM_AL   18432
#define GM_BH   36864
#define GM_BL   46080
#define GM_SMEM 110592

__global__ __launch_bounds__(256) void gemm_mma_kernel(
    const float* __restrict__ bq, const float* __restrict__ bk,
    const float* __restrict__ bv, const float* __restrict__ bo,
    float* __restrict__ outp, int modebase)
{
    extern __shared__ __align__(16) unsigned char smem[];
    uint32_t sbase = smem_u32(smem);

    int tid = threadIdx.x;
    int wid = tid >> 5, lane = tid & 31;
    int wm = wid & 3, wn = wid >> 2;

    int mode = modebase + blockIdx.z;
    const float* bias;
    unsigned short *dsth, *dstl;
    if      (mode == 0) { bias = bq; dsth = g_qh; dstl = g_ql; }
    else if (mode == 1) { bias = bk; dsth = g_kh; dstl = g_kl; }
    else if (mode == 2) { bias = bv; dsth = g_vh; dstl = g_vl; }
    else                { bias = bo; dsth = 0;    dstl = 0;    }

    const unsigned short* Ah = (mode < 3) ? g_ah : g_ch;
    const unsigned short* Al = (mode < 3) ? g_al : g_cl;
    int widx = (mode < 3) ? mode : 3;
    const unsigned short* Bh = g_wth + (size_t)widx*512*512;
    const unsigned short* Bl = g_wtl + (size_t)widx*512*512;

    int n0   = blockIdx.x * 64;
    int row0 = blockIdx.y * 128;

    float acc[2][4][4];
    #pragma unroll
    for (int mi = 0; mi < 2; mi++)
        #pragma unroll
        for (int ni = 0; ni < 4; ni++)
            #pragma unroll
            for (int c = 0; c < 4; c++) acc[mi][ni][c] = 0.f;

    // cp.async chunk fill: A 8 iters, B 4 iters per thread
    auto issue_chunk = [&](int kb, uint32_t bufo) {
        int kbase = kb * 64;
        #pragma unroll
        for (int i = 0; i < 8; i++) {
            int idx = i*256 + tid;
            int a = idx >> 10;
            int rem = idx & 1023;
            int row = rem >> 3, q8 = rem & 7;
            const unsigned short* srcp = a ? Al : Ah;
            CP_ASYNC16(sbase + bufo + (a ? GM_AL : GM_AH) + row*144 + q8*16,
                       &srcp[(size_t)(row0+row)*512 + kbase + q8*8]);
        }
        #pragma unroll
        for (int i = 0; i < 4; i++) {
            int idx = i*256 + tid;
            int a = idx >> 9;
            int rem = idx & 511;
            int row = rem >> 3, q8 = rem & 7;
            const unsigned short* srcp = a ? Bl : Bh;
            CP_ASYNC16(sbase + bufo + (a ? GM_BL : GM_BH) + row*144 + q8*16,
                       &srcp[(size_t)(n0+row)*512 + kbase + q8*8]);
        }
        CP_COMMIT();
    };

    issue_chunk(0, 0);

    for (int kb = 0; kb < 8; kb++) {
        uint32_t bufo = (kb & 1) ? GM_BUF : 0;
        CP_WAIT0();
        __syncthreads();
        if (kb + 1 < 8)
            issue_chunk(kb + 1, ((kb + 1) & 1) ? GM_BUF : 0);

        #pragma unroll
        for (int ks = 0; ks < 4; ks++) {
            uint32_t a_hi[2][4], a_lo[2][4], b_hi[8], b_lo[8];
            #pragma unroll
            for (int mi = 0; mi < 2; mi++) {
                int row = wm*32 + mi*16 + (lane & 15);
                int kcol = ks*16 + ((lane >> 4) << 3);
                uint32_t off = bufo + (uint32_t)(row*(AS_*2) + kcol*2);
                ldsm_x4(a_hi[mi][0], a_hi[mi][1], a_hi[mi][2], a_hi[mi][3],
                        sbase + GM_AH + off);
                ldsm_x4(a_lo[mi][0], a_lo[mi][1], a_lo[mi][2], a_lo[mi][3],
                        sbase + GM_AL + off);
            }
            #pragma unroll
            for (int g = 0; g < 2; g++) {
                int rr = lane & 7;
                int hk = (lane >> 3) & 1;
                int hn = (lane >> 4) & 1;
                int nrow = wn*32 + g*16 + hn*8 + rr;
                int kcol = ks*16 + hk*8;
                uint32_t off = bufo + (uint32_t)(nrow*(AS_*2) + kcol*2);
                ldsm_x4(b_hi[g*4+0], b_hi[g*4+1], b_hi[g*4+2], b_hi[g*4+3],
                        sbase + GM_BH + off);
                ldsm_x4(b_lo[g*4+0], b_lo[g*4+1], b_lo[g*4+2], b_lo[g*4+3],
                        sbase + GM_BL + off);
            }
            #pragma unroll
            for (int mi = 0; mi < 2; mi++) {
                #pragma unroll
                for (int ni = 0; ni < 4; ni++) {
                    mma_bf16(acc[mi][ni], a_hi[mi], &b_hi[ni*2]);
                    mma_bf16(acc[mi][ni], a_lo[mi], &b_hi[ni*2]);
                    mma_bf16(acc[mi][ni], a_hi[mi], &b_lo[ni*2]);
                }
            }
        }
    }

    float scale = (mode == 0) ? 0.125f : 1.f;
    #pragma unroll
    for (int mi = 0; mi < 2; mi++) {
        #pragma unroll
        for (int ni = 0; ni < 4; ni++) {
            int nl = wn*32 + ni*8 + (lane & 3)*2;
            float b0 = bias[n0 + nl], b1 = bias[n0 + nl + 1];
            #pragma unroll
            for (int half = 0; half < 2; half++) {
                int m = row0 + wm*32 + mi*16 + (lane >> 2) + half*8;
                float ox = (acc[mi][ni][half*2+0] + b0) * scale;
                float oy = (acc[mi][ni][half*2+1] + b1) * scale;
                if (mode < 3) {
                    int enc = m >> 12, b = (m >> 10) & 3, l = m & 1023;
                    int h = n0 >> 6;
                    size_t idx = ((((size_t)(enc*B_ + b))*H_ + h)*L_ + l)*HD_ + nl;
                    uint32_t hi, lo;
                    split2(ox, oy, hi, lo);
                    *(uint32_t*)&dsth[idx] = hi;
                    *(uint32_t*)&dstl[idx] = lo;
                } else {
                    float2 o; o.x = ox; o.y = oy;
                    *(float2*)&outp[(size_t)m*D_ + n0 + nl] = o;
                }
            }
        }
    }
}

// ===========================================================================
// Flash attention, cp.async double-buffered K/V ring; Q smem reused as slot 1.
//   grid (16 qtiles, 32 b*h, 2 dirs), 128 threads (4 warps).
// Stage layout (within KV buffer): KH 0, KL 9216, VH 18432, VL 27648; 36864/st.
// Q loaded at offset 36864 (slot 1 region) — frags extracted before slot 1 use.
// ===========================================================================
#define AT_BUF  36864
#define AT_KH   0
#define AT_KL   9216
#define AT_VH   18432
#define AT_VL   27648
#define AT_SMEM 73728

__global__ __launch_bounds__(128) void attn_mma_kernel()
{
    extern __shared__ __align__(16) unsigned char smem[];
    uint32_t sbase = smem_u32(smem);

    int tid = threadIdx.x;
    int wid = tid >> 5, lane = tid & 31;
    int r = lane >> 2, cq = lane & 3;

    int qt = blockIdx.x, bh = blockIdx.y, dir = blockIdx.z;
    int b = bh >> 3, h = bh & 7;
    int enc_q = dir, enc_kv = 1 - dir;

    size_t qoff  = ((size_t)((enc_q *B_ + b)*H_ + h))*L_*HD_;
    size_t kvoff = ((size_t)((enc_kv*B_ + b)*H_ + h))*L_*HD_;
    const unsigned short* Qh = g_qh + qoff;
    const unsigned short* Ql = g_ql + qoff;
    const unsigned short* Kh = g_kh + kvoff;
    const unsigned short* Kl = g_kl + kvoff;
    const unsigned short* Vh = g_vh + kvoff;
    const unsigned short* Vl = g_vl + kvoff;
    const float* mb = g_mb + ((size_t)dir*B_ + b)*L_*L_;
    int q0 = qt * 64;

    // ---- Q cp.async into slot-1 region ----
    #pragma unroll
    for (int i = 0; i < 8; i++) {
        int idx = i*128 + tid;
        int a = idx >> 9;
        int rem = idx & 511;
        int row = rem >> 3, q8 = rem & 7;
        const unsigned short* srcp = a ? Ql : Qh;
        CP_ASYNC16(sbase + AT_BUF + (a ? 9216 : 0) + row*144 + q8*16,
                   &srcp[(size_t)(q0+row)*HD_ + q8*8]);
    }
    CP_COMMIT();
    CP_WAIT0();
    __syncthreads();

    auto issue_kv = [&](int t, uint32_t bufo) {
        int k0 = t * 64;
        #pragma unroll
        for (int i = 0; i < 16; i++) {
            int idx = i*128 + tid;
            int a = idx >> 9;
            int rem = idx & 511;
            int row = rem >> 3, q8 = rem & 7;
            const unsigned short* srcp = (a == 0) ? Kh : (a == 1) ? Kl
                                       : (a == 2) ? Vh : Vl;
            int dsto = (a == 0) ? AT_KH : (a == 1) ? AT_KL
                     : (a == 2) ? AT_VH : AT_VL;
            CP_ASYNC16(sbase + bufo + dsto + row*144 + q8*16,
                       &srcp[(size_t)(k0+row)*HD_ + q8*8]);
        }
        CP_COMMIT();
    };

    // prefetch tile 0 into slot 0 (Q frag extraction overlaps this copy)
    issue_kv(0, 0);

    // ---- Q A-fragments resident in regs (read from slot-1 region) ----
    uint32_t aq_h[4][4], aq_l[4][4];
    #pragma unroll
    for (int ks = 0; ks < 4; ks++) {
        int row = wid*16 + (lane & 15);
        int kcol = ks*16 + ((lane >> 4) << 3);
        uint32_t off = (uint32_t)(row*(AS_*2) + kcol*2);
        ldsm_x4(aq_h[ks][0], aq_h[ks][1], aq_h[ks][2], aq_h[ks][3],
                sbase + AT_BUF + off);
        ldsm_x4(aq_l[ks][0], aq_l[ks][1], aq_l[ks][2], aq_l[ks][3],
                sbase + AT_BUF + 9216 + off);
    }

    float o_acc[8][4];
    #pragma unroll
    for (int nt = 0; nt < 8; nt++)
        #pragma unroll
        for (int c = 0; c < 4; c++) o_acc[nt][c] = 0.f;
    float m0r = -3.0e38f, m1r = -3.0e38f, l0r = 0.f, l1r = 0.f;

    int qg0 = q0 + wid*16 + r;
    int qg1 = qg0 + 8;
    const float* mb0 = mb + (size_t)qg0*L_ + cq*2;
    const float* mb1 = mb + (size_t)qg1*L_ + cq*2;

    for (int t = 0; t < 16; t++) {
        int k0 = t * 64;
        uint32_t bufo = (t & 1) ? AT_BUF : 0;
        CP_WAIT0();
        __syncthreads();          // tile t ready; prior reads of other slot done
        if (t + 1 < 16)
            issue_kv(t + 1, ((t + 1) & 1) ? AT_BUF : 0);

        // ---- prefetch mask+bias into regs (hidden under QK MMAs) ----
        float2 mbv0[8], mbv1[8];
        #pragma unroll
        for (int nt = 0; nt < 8; nt++) {
            int cc = k0 + nt*8;
            mbv0[nt] = *(const float2*)&mb0[cc];
            mbv1[nt] = *(const float2*)&mb1[cc];
        }

        // ---- S = Q K^T ----
        float s_acc[8][4];
        #pragma unroll
        for (int nt = 0; nt < 8; nt++)
            #pragma unroll
            for (int c = 0; c < 4; c++) s_acc[nt][c] = 0.f;

        #pragma unroll
        for (int ks = 0; ks < 4; ks++) {
            #pragma unroll
            for (int g = 0; g < 4; g++) {
                uint32_t bk_h[4], bk_l[4];
                int rr = lane & 7;
                int hk = (lane >> 3) & 1;
                int hn = (lane >> 4) & 1;
                int nrow = g*16 + hn*8 + rr;
                int kcol = ks*16 + hk*8;
                uint32_t off = bufo + (uint32_t)(nrow*(AS_*2) + kcol*2);
                ldsm_x4(bk_h[0], bk_h[1], bk_h[2], bk_h[3], sbase + AT_KH + off);
                ldsm_x4(bk_l[0], bk_l[1], bk_l[2], bk_l[3], sbase + AT_KL + off);
                #pragma unroll
                for (int sub = 0; sub < 2; sub++) {
                    int nt = g*2 + sub;
                    mma_bf16(s_acc[nt], aq_h[ks], &bk_h[sub*2]);
                    mma_bf16(s_acc[nt], aq_l[ks], &bk_h[sub*2]);
                    mma_bf16(s_acc[nt], aq_h[ks], &bk_l[sub*2]);
                }
            }
        }

        // ---- additive mask+bias (from prefetched regs) ----
        #pragma unroll
        for (int nt = 0; nt < 8; nt++) {
            s_acc[nt][0] += mbv0[nt].x;
            s_acc[nt][1] += mbv0[nt].y;
            s_acc[nt][2] += mbv1[nt].x;
            s_acc[nt][3] += mbv1[nt].y;
        }

        // ---- online softmax ----
        float mx0 = -3.0e38f, mx1 = -3.0e38f;
        #pragma unroll
        for (int nt = 0; nt < 8; nt++) {
            mx0 = fmaxf(mx0, fmaxf(s_acc[nt][0], s_acc[nt][1]));
            mx1 = fmaxf(mx1, fmaxf(s_acc[nt][2], s_acc[nt][3]));
        }
        mx0 = fmaxf(mx0, __shfl_xor_sync(0xffffffffu, mx0, 1));
        mx0 = fmaxf(mx0, __shfl_xor_sync(0xffffffffu, mx0, 2));
        mx1 = fmaxf(mx1, __shfl_xor_sync(0xffffffffu, mx1, 1));
        mx1 = fmaxf(mx1, __shfl_xor_sync(0xffffffffu, mx1, 2));

        float mn0 = fmaxf(m0r, mx0);
        float mn1 = fmaxf(m1r, mx1);
        float c0 = __expf(m0r - mn0);
        float c1 = __expf(m1r - mn1);
        m0r = mn0; m1r = mn1;

        float rs0 = 0.f, rs1 = 0.f;
        #pragma unroll
        for (int nt = 0; nt < 8; nt++) {
            s_acc[nt][0] = __expf(s_acc[nt][0] - m0r); rs0 += s_acc[nt][0];
            s_acc[nt][1] = __expf(s_acc[nt][1] - m0r); rs0 += s_acc[nt][1];
            s_acc[nt][2] = __expf(s_acc[nt][2] - m1r); rs1 += s_acc[nt][2];
            s_acc[nt][3] = __expf(s_acc[nt][3] - m1r); rs1 += s_acc[nt][3];
        }
        rs0 += __shfl_xor_sync(0xffffffffu, rs0, 1);
        rs0 += __shfl_xor_sync(0xffffffffu, rs0, 2);
        rs1 += __shfl_xor_sync(0xffffffffu, rs1, 1);
        rs1 += __shfl_xor_sync(0xffffffffu, rs1, 2);
        l0r = l0r*c0 + rs0;
        l1r = l1r*c1 + rs1;

        #pragma unroll
        for (int nt = 0; nt < 8; nt++) {
            o_acc[nt][0] *= c0; o_acc[nt][1] *= c0;
            o_acc[nt][2] *= c1; o_acc[nt][3] *= c1;
        }

        // ---- O += P V (P split in regs) ----
        #pragma unroll
        for (int ks = 0; ks < 4; ks++) {
            int t0 = 2*ks, t1 = 2*ks + 1;
            uint32_t ap_h[4], ap_l[4];
            split2(s_acc[t0][0], s_acc[t0][1], ap_h[0], ap_l[0]);
            split2(s_acc[t0][2], s_acc[t0][3], ap_h[1], ap_l[1]);
            split2(s_acc[t1][0], s_acc[t1][1], ap_h[2], ap_l[2]);
            split2(s_acc[t1][2], s_acc[t1][3], ap_h[3], ap_l[3]);
            #pragma unroll
            for (int g = 0; g < 4; g++) {
                uint32_t bv_h[4], bv_l[4];
                int kk  = ks*16 + ((lane >> 3) & 1)*8 + (lane & 7);
                int hdo = g*16 + ((lane >> 4) & 1)*8;
                uint32_t off = bufo + (uint32_t)(kk*(AS_*2) + hdo*2);
                ldsm_x4_t(bv_h[0], bv_h[1], bv_h[2], bv_h[3], sbase + AT_VH + off);
                ldsm_x4_t(bv_l[0], bv_l[1], bv_l[2], bv_l[3], sbase + AT_VL + off);
                #pragma unroll
                for (int sub = 0; sub < 2; sub++) {
                    int nt = g*2 + sub;
                    mma_bf16(o_acc[nt], ap_h, &bv_h[sub*2]);
                    mma_bf16(o_acc[nt], ap_l, &bv_h[sub*2]);
                    mma_bf16(o_acc[nt], ap_h, &bv_l[sub*2]);
                }
            }
        }
    }

    // ---- finalize: ctx = O/l as bf16 hi/lo ----
    float inv0 = 1.f / l0r;
    float inv1 = 1.f / l1r;
    size_t base0 = ((size_t)(enc_q*B_ + b)*L_ + qg0)*D_ + h*64 + cq*2;
    size_t base1 = ((size_t)(enc_q*B_ + b)*L_ + qg1)*D_ + h*64 + cq*2;
    #pragma unroll
    for (int nt = 0; nt < 8; nt++) {
        uint32_t hi0, lo0, hi1, lo1;
        split2(o_acc[nt][0]*inv0, o_acc[nt][1]*inv0, hi0, lo0);
        split2(o_acc[nt][2]*inv1, o_acc[nt][3]*inv1, hi1, lo1);
        *(uint32_t*)&g_ch[base0 + nt*8] = hi0;
        *(uint32_t*)&g_cl[base0 + nt*8] = lo0;
        *(uint32_t*)&g_ch[base1 + nt*8] = hi1;
        *(uint32_t*)&g_cl[base1 + nt*8] = lo1;
    }
}

// ---------------------------------------------------------------------------
extern "C" void kernel_launch(void* const* d_in, const int* in_sizes, int n_in,
                              void* d_out, int out_size)
{
    const float* u_enc     = (const float*)d_in[0];
    const float* e_enc     = (const float*)d_in[1];
    const float* logit_bpp = (const float*)d_in[2];
    const void*  ue_mask   = d_in[3];
    const void*  eu_mask   = d_in[4];
    const float* wq_k = (const float*)d_in[5];
    const float* wq_b = (const float*)d_in[6];
    const float* wk_k = (const float*)d_in[7];
    const float* wk_b = (const float*)d_in[8];
    const float* wv_k = (const float*)d_in[9];
    const float* wv_b = (const float*)d_in[10];
    const float* wo_k = (const float*)d_in[11];
    const float* wo_b = (const float*)d_in[12];
    const float* bpp_w = (const float*)d_in[13];
    const float* bpp_b = (const float*)d_in[14];
    float* out = (float*)d_out;

    cudaFuncSetAttribute((const void*)attn_mma_kernel,
                         cudaFuncAttributeMaxDynamicSharedMemorySize, AT_SMEM);
    cudaFuncSetAttribute((const void*)gemm_mma_kernel,
                         cudaFuncAttributeMaxDynamicSharedMemorySize, GM_SMEM);

    // 0) mask dtype detection
    mask_detect_kernel<<<1, 256>>>((const unsigned int*)ue_mask);
    // 1) bias prep then fused mask+bias
    bpp_prep_kernel<<<dim3(32, 32), dim3(32, 8)>>>(logit_bpp, bpp_w, bpp_b);
    maskbias_kernel<<<dim3(4096, 1, 2), 256>>>(ue_mask, eu_mask);
    // 2) one-time operand splits
    enc_split_kernel<<<dim3(1024, 1, 2), 256>>>(u_enc, e_enc);
    wt_split_kernel<<<dim3(16, 16, 4), dim3(32, 8)>>>(wq_k, wk_k, wv_k, wo_k);
    // 3) fused QKV projections (z: 0=q,1=k,2=v) -> bf16 hi/lo
    gemm_mma_kernel<<<dim3(8, 64, 3), 256, GM_SMEM>>>(wq_b, wk_b, wv_b, wo_b,
                                                      nullptr, 0);
    // 4) fused attention, both directions -> ctx bf16 hi/lo
    attn_mma_kernel<<<dim3(16, 32, 2), 128, AT_SMEM>>>();
    // 5) output projection -> d_out
    gemm_mma_kernel<<<dim3(8, 64, 1), 256, GM_SMEM>>>(wq_b, wk_b, wv_b, wo_b,
                                                      out, 3);
}